// round 2
// baseline (speedup 1.0000x reference)
#include <cuda_runtime.h>

typedef unsigned long long ull;

#define Bn   16384
#define Tn   24
#define KZX  1056
#define INd  1060
#define G3   384
#define NC   512

// scratch: cols 0..383 = gi_base (+b_ih, +b_hh for cols<256, +rel terms), cols 384..511 = h0
__device__ __align__(16) float g_sc[(size_t)Bn * NC];

__device__ __forceinline__ ull pk2(float x, float y) {
    ull r; asm("mov.b64 %0, {%1,%2};" : "=l"(r) : "f"(x), "f"(y)); return r;
}
__device__ __forceinline__ float2 up2(ull v) {
    float2 r; asm("mov.b64 {%0,%1}, %2;" : "=f"(r.x), "=f"(r.y) : "l"(v)); return r;
}
__device__ __forceinline__ void fma2(ull &d, ull a, ull b) {
    asm("fma.rn.f32x2 %0, %1, %2, %0;" : "+l"(d) : "l"(a), "l"(b));
}
__device__ __forceinline__ ull mul2(ull a, ull b) {
    ull r; asm("mul.rn.f32x2 %0, %1, %2;" : "=l"(r) : "l"(a), "l"(b)); return r;
}
__device__ __forceinline__ float sigf(float x) {
    return __fdividef(1.f, 1.f + __expf(-x));
}
__device__ __forceinline__ float tanha(float x) {
    return __fdividef(2.f, 1.f + __expf(-2.f * x)) - 1.f;
}

// ---------------------------------------------------------------------------
// Phase 1: C(B x 512) = zx(B x 1056) @ [W_ih[:, :1056] ; W_dh]^T + epilogue
// 128x128 tile, BK=8, 256 threads, 8x8 per thread, f32x2-packed accumulators.
// ---------------------------------------------------------------------------
__global__ __launch_bounds__(256, 2) void phase1(
    const float* __restrict__ enc, const float* __restrict__ zin,
    const float* __restrict__ W_ih, const float* __restrict__ b_ih,
    const float* __restrict__ W_dh, const float* __restrict__ b_dh,
    const float* __restrict__ b_hh,
    const float* __restrict__ lobs, const float* __restrict__ sg)
{
    __shared__ __align__(16) float As[8][132];
    __shared__ __align__(16) float Bs[8][132];
    __shared__ float colb[128], c58[128], c59[128];

    int tid  = threadIdx.x;
    int m0   = blockIdx.y * 128;
    int n0   = blockIdx.x * 128;
    int lrow = tid >> 1;
    int lkq  = (tid & 1) * 4;
    int ti   = (tid >> 4) * 8;
    int tj   = (tid & 15) * 8;

    ull acc[8][4];
    #pragma unroll
    for (int i = 0; i < 8; i++)
        #pragma unroll
        for (int c = 0; c < 4; c++) acc[i][c] = 0ULL;

    int am = m0 + lrow;
    int bj = n0 + lrow;
    const float* brow = (bj < G3) ? (W_ih + (size_t)bj * INd)
                                  : (W_dh + (size_t)(bj - G3) * KZX);
    const float* arow_e = enc + (size_t)am * 1024;
    const float* arow_z = zin + (size_t)am * 32;

    for (int k0 = 0; k0 < KZX; k0 += 8) {
        int kk = k0 + lkq;
        float4 av = (kk < 1024) ? *(const float4*)(arow_e + kk)
                                : *(const float4*)(arow_z + (kk - 1024));
        As[lkq + 0][lrow] = av.x; As[lkq + 1][lrow] = av.y;
        As[lkq + 2][lrow] = av.z; As[lkq + 3][lrow] = av.w;
        float4 bv = *(const float4*)(brow + kk);
        Bs[lkq + 0][lrow] = bv.x; Bs[lkq + 1][lrow] = bv.y;
        Bs[lkq + 2][lrow] = bv.z; Bs[lkq + 3][lrow] = bv.w;
        __syncthreads();
        #pragma unroll
        for (int k = 0; k < 8; k++) {
            float a[8];
            *(float4*)&a[0] = *(const float4*)&As[k][ti];
            *(float4*)&a[4] = *(const float4*)&As[k][ti + 4];
            ull bp[4];
            #pragma unroll
            for (int c = 0; c < 4; c++)
                bp[c] = *(const ull*)&Bs[k][tj + 2 * c];
            #pragma unroll
            for (int i = 0; i < 8; i++) {
                ull ap = pk2(a[i], a[i]);
                #pragma unroll
                for (int c = 0; c < 4; c++) fma2(acc[i][c], ap, bp[c]);
            }
        }
        __syncthreads();
    }

    bool is_gi = (n0 < G3);
    if (tid < 128) {
        int j = n0 + tid;
        if (is_gi) {
            colb[tid] = b_ih[j] + ((n0 < 256) ? b_hh[j] : 0.f);
            c58[tid]  = W_ih[(size_t)j * INd + 1058];
            c59[tid]  = W_ih[(size_t)j * INd + 1059];
        } else {
            colb[tid] = b_dh[j - G3];
            c58[tid]  = 0.f;
            c59[tid]  = 0.f;
        }
    }
    __syncthreads();

    const float inv_dt = 1.0f / 4.8f;
    #pragma unroll
    for (int i = 0; i < 8; i++) {
        int m = m0 + ti + i;
        float r0v = 0.f, r1v = 0.f;
        if (is_gi) {
            r0v = (sg[m * 2 + 0] - lobs[m * 6 + 0]) * inv_dt;
            r1v = (sg[m * 2 + 1] - lobs[m * 6 + 1]) * inv_dt;
        }
        #pragma unroll
        for (int c = 0; c < 4; c++) {
            float2 v = up2(acc[i][c]);
            int jj = tj + 2 * c;
            v.x += colb[jj]     + r0v * c58[jj]     + r1v * c59[jj];
            v.y += colb[jj + 1] + r0v * c58[jj + 1] + r1v * c59[jj + 1];
            *(float2*)&g_sc[(size_t)m * NC + n0 + jj] = v;
        }
    }
}

// ---------------------------------------------------------------------------
// Phase 2: GRU recurrence. 64 rows/block (8 warps x 8 rows, warp-autonomous),
// W_hh transposed in smem (stride 386), per-warp h rows in smem (stride 130).
// No block-level syncs inside the 24-step loop.
// ---------------------------------------------------------------------------
#define SWT 386
#define SH  130
#define RPW 8

__global__ __launch_bounds__(256, 1) void phase2(
    const float* __restrict__ W_hh, const float* __restrict__ W_ih,
    const float* __restrict__ b_hh,
    const float* __restrict__ W_mu, const float* __restrict__ b_mu,
    const float* __restrict__ W_std, const float* __restrict__ b_std,
    const float* __restrict__ lobs, const float* __restrict__ W_vel,
    const float* __restrict__ b_vel, const float* __restrict__ fut,
    float* __restrict__ out)
{
    extern __shared__ __align__(16) float sm[];
    float* Wt = sm;                  // [128][386]
    float* hs = Wt + 128 * SWT;      // [64][130]

    int tid = threadIdx.x;
    int tx  = tid & 31, wid = tid >> 5;
    int rb  = blockIdx.x * 64;
    int wr0 = wid * RPW;
    int jc  = 2 * tx;

    // stage W_hh transposed: Wt[k][j] = W_hh[j*128+k]
    for (int i = tid; i < G3 * 128; i += 256)
        Wt[(i & 127) * SWT + (i >> 7)] = W_hh[i];
    // stage h0
    for (int i = tid; i < 64 * 128; i += 256) {
        int row = i >> 7, k = i & 127;
        hs[row * SH + k] = g_sc[(size_t)(rb + row) * NC + G3 + k];
    }
    __syncthreads();

    // per-thread constants: a-columns (1056,1057) of W_ih at this thread's 12 cols
    ull w56[6], w57[6];
    #pragma unroll
    for (int c = 0; c < 6; c++) {
        int j = jc + 64 * c;
        w56[c] = pk2(__ldg(&W_ih[(size_t)j * INd + 1056]),
                     __ldg(&W_ih[(size_t)(j + 1) * INd + 1056]));
        w57[c] = pk2(__ldg(&W_ih[(size_t)j * INd + 1057]),
                     __ldg(&W_ih[(size_t)(j + 1) * INd + 1057]));
    }
    // b_hh at this thread's n-cols (goes inside r*(...) in the tanh)
    ull bhn[2];
    #pragma unroll
    for (int p = 0; p < 2; p++) {
        int j = 256 + jc + 64 * p;
        bhn[p] = pk2(__ldg(&b_hh[j]), __ldg(&b_hh[j + 1]));
    }

    // h in registers (this thread's 4 cols per row)
    ull hold[RPW][2];
    #pragma unroll
    for (int r = 0; r < RPW; r++) {
        const float* gp = &g_sc[(size_t)(rb + wr0 + r) * NC + G3 + jc];
        float2 h0a = *(const float2*)gp;
        float2 h0b = *(const float2*)(gp + 64);
        hold[r][0] = pk2(h0a.x, h0a.y);
        hold[r][1] = pk2(h0b.x, h0b.y);
    }

    // a at t=0: last_obs @ W_vel^T + b_vel
    float2 a0f[RPW];
    #pragma unroll
    for (int r = 0; r < RPW; r++) {
        int b = rb + wr0 + r;
        float s0 = b_vel[0], s1 = b_vel[1];
        #pragma unroll
        for (int q = 0; q < 6; q++) {
            float lv = __ldg(&lobs[b * 6 + q]);
            s0 = fmaf(lv, W_vel[q], s0);
            s1 = fmaf(lv, W_vel[6 + q], s1);
        }
        a0f[r] = make_float2(s0, s1);
    }

    const int mrow = tx >> 2, mo = tx & 3;
    const float* wv = (mo < 2) ? (W_mu + mo * 128) : (W_std + (mo - 2) * 128);
    const float mb  = (mo < 2) ? b_mu[mo] : b_std[mo - 2];
    size_t obase = (mo < 2 ? (size_t)0 : (size_t)Tn * Bn * 2)
                 + (size_t)(rb + wr0 + mrow) * 2 + (mo & 1);

    for (int t = 0; t < Tn; t++) {
        float2 af[RPW];
        if (t == 0) {
            #pragma unroll
            for (int r = 0; r < RPW; r++) af[r] = a0f[r];
        } else {
            #pragma unroll
            for (int r = 0; r < RPW; r++)
                af[r] = *(const float2*)&fut[((size_t)(t - 1) * Bn + rb + wr0 + r) * 6 + 2];
        }

        // acc = gh partial; a-correction folded into r/z cols only (summed gates)
        ull acc[RPW][6];
        #pragma unroll
        for (int r = 0; r < RPW; r++) {
            ull a0p = pk2(af[r].x, af[r].x);
            ull a1p = pk2(af[r].y, af[r].y);
            #pragma unroll
            for (int c = 0; c < 4; c++) {
                acc[r][c] = mul2(a0p, w56[c]);
                fma2(acc[r][c], a1p, w57[c]);
            }
            acc[r][4] = 0ULL; acc[r][5] = 0ULL;
        }

        // acc += h @ W_hh^T  (warp's 8 rows, thread's 12 cols)
        const float* hb = &hs[wr0 * SH];
        #pragma unroll 2
        for (int k2 = 0; k2 < 64; k2++) {
            float2 hv[RPW];
            #pragma unroll
            for (int r = 0; r < RPW; r++)
                hv[r] = *(const float2*)(hb + r * SH + 2 * k2);
            const float* wrow = &Wt[(2 * k2) * SWT + jc];
            ull wA[6], wB[6];
            #pragma unroll
            for (int c = 0; c < 6; c++) {
                wA[c] = *(const ull*)(wrow + 64 * c);
                wB[c] = *(const ull*)(wrow + SWT + 64 * c);
            }
            #pragma unroll
            for (int r = 0; r < RPW; r++) {
                ull hx = pk2(hv[r].x, hv[r].x);
                ull hy = pk2(hv[r].y, hv[r].y);
                #pragma unroll
                for (int c = 0; c < 6; c++) {
                    fma2(acc[r][c], hx, wA[c]);
                    fma2(acc[r][c], hy, wB[c]);
                }
            }
        }

        // gates
        #pragma unroll
        for (int r = 0; r < RPW; r++) {
            const float* gp = &g_sc[(size_t)(rb + wr0 + r) * NC + jc];
            ull a0p = pk2(af[r].x, af[r].x);
            ull a1p = pk2(af[r].y, af[r].y);
            #pragma unroll
            for (int p = 0; p < 2; p++) {
                float2 gir = *(const float2*)(gp + 64 * p);
                float2 giz = *(const float2*)(gp + 128 + 64 * p);
                float2 gin = *(const float2*)(gp + 256 + 64 * p);
                ull anc = mul2(a0p, w56[p + 4]);   // a-corr for n-cols: input side
                fma2(anc, a1p, w57[p + 4]);
                float2 an  = up2(anc);
                float2 ghr = up2(acc[r][p]);
                float2 ghz = up2(acc[r][p + 2]);
                float2 ghn = up2(acc[r][p + 4]);
                float2 bh  = up2(bhn[p]);
                float rgx = sigf(gir.x + ghr.x), rgy = sigf(gir.y + ghr.y);
                float zgx = sigf(giz.x + ghz.x), zgy = sigf(giz.y + ghz.y);
                float nx = tanha(gin.x + an.x + rgx * (ghn.x + bh.x));
                float ny = tanha(gin.y + an.y + rgy * (ghn.y + bh.y));
                float2 ho = up2(hold[r][p]);
                float hxn = (1.f - zgx) * nx + zgx * ho.x;
                float hyn = (1.f - zgy) * ny + zgy * ho.y;
                hold[r][p] = pk2(hxn, hyn);
                *(float2*)&hs[(wr0 + r) * SH + jc + 64 * p] = make_float2(hxn, hyn);
            }
        }
        __syncwarp();

        // mu / std: lane -> (row = tx>>2, out = tx&3); out 0,1 = mu, 2,3 = std
        float s0 = 0.f, s1 = 0.f;
        const float* hp = &hs[(wr0 + mrow) * SH];
        #pragma unroll 8
        for (int k2 = 0; k2 < 64; k2++) {
            float2 h2 = *(const float2*)(hp + 2 * k2);
            float2 w2 = *(const float2*)(wv + 2 * k2);
            s0 = fmaf(h2.x, w2.x, s0);
            s1 = fmaf(h2.y, w2.y, s1);
        }
        float sv = s0 + s1 + mb;
        out[obase + (size_t)t * Bn * 2] = (mo < 2) ? sv : __expf(0.5f * sv);
        __syncwarp();
    }
}

extern "C" void kernel_launch(void* const* d_in, const int* in_sizes, int n_in,
                              void* d_out, int out_size) {
    const float* lobs  = (const float*)d_in[0];
    const float* enc   = (const float*)d_in[1];
    const float* zin   = (const float*)d_in[2];
    const float* sg    = (const float*)d_in[3];
    const float* fut   = (const float*)d_in[4];
    const float* W_dh  = (const float*)d_in[5];
    const float* b_dh  = (const float*)d_in[6];
    const float* W_vel = (const float*)d_in[7];
    const float* b_vel = (const float*)d_in[8];
    const float* W_ih  = (const float*)d_in[9];
    const float* b_ih  = (const float*)d_in[10];
    const float* W_hh  = (const float*)d_in[11];
    const float* b_hh  = (const float*)d_in[12];
    const float* W_mu  = (const float*)d_in[13];
    const float* b_mu  = (const float*)d_in[14];
    const float* W_std = (const float*)d_in[15];
    const float* b_std = (const float*)d_in[16];
    float* out = (float*)d_out;

    phase1<<<dim3(4, 128), 256>>>(enc, zin, W_ih, b_ih, W_dh, b_dh, b_hh, lobs, sg);

    int smem = (128 * SWT + 64 * SH) * 4;
    cudaFuncSetAttribute(phase2, cudaFuncAttributeMaxDynamicSharedMemorySize, smem);
    phase2<<<256, 256, smem>>>(W_hh, W_ih, b_hh, W_mu, b_mu, W_std, b_std,
                               lobs, W_vel, b_vel, fut, out);
}

// round 3
// speedup vs baseline: 1.0014x; 1.0014x over previous
#include <cuda_runtime.h>

typedef unsigned long long ull;

#define Bn   16384
#define Tn   24
#define KZX  1056
#define INd  1060
#define G3   384
#define NC   512

// scratch: cols 0..383 = gi_base (+b_ih, +b_hh for cols<256, +rel terms), cols 384..511 = h0
__device__ __align__(16) float g_sc[(size_t)Bn * NC];

__device__ __forceinline__ ull pk2(float x, float y) {
    ull r; asm("mov.b64 %0, {%1,%2};" : "=l"(r) : "f"(x), "f"(y)); return r;
}
__device__ __forceinline__ float2 up2(ull v) {
    float2 r; asm("mov.b64 {%0,%1}, %2;" : "=f"(r.x), "=f"(r.y) : "l"(v)); return r;
}
__device__ __forceinline__ void fma2(ull &d, ull a, ull b) {
    asm("fma.rn.f32x2 %0, %1, %2, %0;" : "+l"(d) : "l"(a), "l"(b));
}
__device__ __forceinline__ ull mul2(ull a, ull b) {
    ull r; asm("mul.rn.f32x2 %0, %1, %2;" : "=l"(r) : "l"(a), "l"(b)); return r;
}
__device__ __forceinline__ float sigf(float x) {
    return __fdividef(1.f, 1.f + __expf(-x));
}
__device__ __forceinline__ float tanha(float x) {
    return __fdividef(2.f, 1.f + __expf(-2.f * x)) - 1.f;
}

// ---------------------------------------------------------------------------
// Phase 1: C(B x 512) = zx(B x 1056) @ [W_ih[:, :1056] ; W_dh]^T + epilogue
// 128x128 tile, BK=8, 256 threads, 8x8 per thread, f32x2-packed accumulators.
// ---------------------------------------------------------------------------
__global__ __launch_bounds__(256, 2) void phase1(
    const float* __restrict__ enc, const float* __restrict__ zin,
    const float* __restrict__ W_ih, const float* __restrict__ b_ih,
    const float* __restrict__ W_dh, const float* __restrict__ b_dh,
    const float* __restrict__ b_hh,
    const float* __restrict__ lobs, const float* __restrict__ sg)
{
    __shared__ __align__(16) float As[8][132];
    __shared__ __align__(16) float Bs[8][132];
    __shared__ float colb[128], c58[128], c59[128];

    int tid  = threadIdx.x;
    int m0   = blockIdx.y * 128;
    int n0   = blockIdx.x * 128;
    int lrow = tid >> 1;
    int lkq  = (tid & 1) * 4;
    int ti   = (tid >> 4) * 8;
    int tj   = (tid & 15) * 8;

    ull acc[8][4];
    #pragma unroll
    for (int i = 0; i < 8; i++)
        #pragma unroll
        for (int c = 0; c < 4; c++) acc[i][c] = 0ULL;

    int am = m0 + lrow;
    int bj = n0 + lrow;
    const float* brow = (bj < G3) ? (W_ih + (size_t)bj * INd)
                                  : (W_dh + (size_t)(bj - G3) * KZX);
    const float* arow_e = enc + (size_t)am * 1024;
    const float* arow_z = zin + (size_t)am * 32;

    for (int k0 = 0; k0 < KZX; k0 += 8) {
        int kk = k0 + lkq;
        float4 av = (kk < 1024) ? *(const float4*)(arow_e + kk)
                                : *(const float4*)(arow_z + (kk - 1024));
        As[lkq + 0][lrow] = av.x; As[lkq + 1][lrow] = av.y;
        As[lkq + 2][lrow] = av.z; As[lkq + 3][lrow] = av.w;
        float4 bv = *(const float4*)(brow + kk);
        Bs[lkq + 0][lrow] = bv.x; Bs[lkq + 1][lrow] = bv.y;
        Bs[lkq + 2][lrow] = bv.z; Bs[lkq + 3][lrow] = bv.w;
        __syncthreads();
        #pragma unroll
        for (int k = 0; k < 8; k++) {
            float a[8];
            *(float4*)&a[0] = *(const float4*)&As[k][ti];
            *(float4*)&a[4] = *(const float4*)&As[k][ti + 4];
            ull bp[4];
            #pragma unroll
            for (int c = 0; c < 4; c++)
                bp[c] = *(const ull*)&Bs[k][tj + 2 * c];
            #pragma unroll
            for (int i = 0; i < 8; i++) {
                ull ap = pk2(a[i], a[i]);
                #pragma unroll
                for (int c = 0; c < 4; c++) fma2(acc[i][c], ap, bp[c]);
            }
        }
        __syncthreads();
    }

    bool is_gi = (n0 < G3);
    if (tid < 128) {
        int j = n0 + tid;
        if (is_gi) {
            colb[tid] = b_ih[j] + ((n0 < 256) ? b_hh[j] : 0.f);
            c58[tid]  = W_ih[(size_t)j * INd + 1058];
            c59[tid]  = W_ih[(size_t)j * INd + 1059];
        } else {
            colb[tid] = b_dh[j - G3];
            c58[tid]  = 0.f;
            c59[tid]  = 0.f;
        }
    }
    __syncthreads();

    const float inv_dt = 1.0f / 4.8f;
    #pragma unroll
    for (int i = 0; i < 8; i++) {
        int m = m0 + ti + i;
        float r0v = 0.f, r1v = 0.f;
        if (is_gi) {
            r0v = (sg[m * 2 + 0] - lobs[m * 6 + 0]) * inv_dt;
            r1v = (sg[m * 2 + 1] - lobs[m * 6 + 1]) * inv_dt;
        }
        #pragma unroll
        for (int c = 0; c < 4; c++) {
            float2 v = up2(acc[i][c]);
            int jj = tj + 2 * c;
            v.x += colb[jj]     + r0v * c58[jj]     + r1v * c59[jj];
            v.y += colb[jj + 1] + r0v * c58[jj + 1] + r1v * c59[jj + 1];
            *(float2*)&g_sc[(size_t)m * NC + n0 + jj] = v;
        }
    }
}

// ---------------------------------------------------------------------------
// Phase 2: GRU recurrence. 64 rows/block (8 warps x 8 rows, warp-autonomous),
// W_hh transposed in smem (stride 386), per-warp h rows in smem (stride 130).
// No block-level syncs inside the 24-step loop.
// ---------------------------------------------------------------------------
#define SWT 386
#define SH  130
#define RPW 8

__global__ __launch_bounds__(256, 1) void phase2(
    const float* __restrict__ W_hh, const float* __restrict__ W_ih,
    const float* __restrict__ b_hh,
    const float* __restrict__ W_mu, const float* __restrict__ b_mu,
    const float* __restrict__ W_std, const float* __restrict__ b_std,
    const float* __restrict__ lobs, const float* __restrict__ W_vel,
    const float* __restrict__ b_vel, const float* __restrict__ fut,
    float* __restrict__ out)
{
    extern __shared__ __align__(16) float sm[];
    float* Wt = sm;                  // [128][386]
    float* hs = Wt + 128 * SWT;      // [64][130]

    int tid = threadIdx.x;
    int tx  = tid & 31, wid = tid >> 5;
    int rb  = blockIdx.x * 64;
    int wr0 = wid * RPW;
    int jc  = 2 * tx;

    // stage W_hh transposed: Wt[k][j] = W_hh[j*128+k]
    for (int i = tid; i < G3 * 128; i += 256)
        Wt[(i & 127) * SWT + (i >> 7)] = W_hh[i];
    // stage h0
    for (int i = tid; i < 64 * 128; i += 256) {
        int row = i >> 7, k = i & 127;
        hs[row * SH + k] = g_sc[(size_t)(rb + row) * NC + G3 + k];
    }
    __syncthreads();

    // per-thread constants: a-columns (1056,1057) of W_ih at this thread's 12 cols
    ull w56[6], w57[6];
    #pragma unroll
    for (int c = 0; c < 6; c++) {
        int j = jc + 64 * c;
        w56[c] = pk2(__ldg(&W_ih[(size_t)j * INd + 1056]),
                     __ldg(&W_ih[(size_t)(j + 1) * INd + 1056]));
        w57[c] = pk2(__ldg(&W_ih[(size_t)j * INd + 1057]),
                     __ldg(&W_ih[(size_t)(j + 1) * INd + 1057]));
    }
    // b_hh at this thread's n-cols (goes inside r*(...) in the tanh)
    ull bhn[2];
    #pragma unroll
    for (int p = 0; p < 2; p++) {
        int j = 256 + jc + 64 * p;
        bhn[p] = pk2(__ldg(&b_hh[j]), __ldg(&b_hh[j + 1]));
    }

    // h in registers (this thread's 4 cols per row)
    ull hold[RPW][2];
    #pragma unroll
    for (int r = 0; r < RPW; r++) {
        const float* gp = &g_sc[(size_t)(rb + wr0 + r) * NC + G3 + jc];
        float2 h0a = *(const float2*)gp;
        float2 h0b = *(const float2*)(gp + 64);
        hold[r][0] = pk2(h0a.x, h0a.y);
        hold[r][1] = pk2(h0b.x, h0b.y);
    }

    // a at t=0: last_obs @ W_vel^T + b_vel
    float2 a0f[RPW];
    #pragma unroll
    for (int r = 0; r < RPW; r++) {
        int b = rb + wr0 + r;
        float s0 = b_vel[0], s1 = b_vel[1];
        #pragma unroll
        for (int q = 0; q < 6; q++) {
            float lv = __ldg(&lobs[b * 6 + q]);
            s0 = fmaf(lv, W_vel[q], s0);
            s1 = fmaf(lv, W_vel[6 + q], s1);
        }
        a0f[r] = make_float2(s0, s1);
    }

    const int mrow = tx >> 2, mo = tx & 3;
    const float* wv = (mo < 2) ? (W_mu + mo * 128) : (W_std + (mo - 2) * 128);
    const float mb  = (mo < 2) ? b_mu[mo] : b_std[mo - 2];
    size_t obase = (mo < 2 ? (size_t)0 : (size_t)Tn * Bn * 2)
                 + (size_t)(rb + wr0 + mrow) * 2 + (mo & 1);

    for (int t = 0; t < Tn; t++) {
        float2 af[RPW];
        if (t == 0) {
            #pragma unroll
            for (int r = 0; r < RPW; r++) af[r] = a0f[r];
        } else {
            #pragma unroll
            for (int r = 0; r < RPW; r++)
                af[r] = *(const float2*)&fut[((size_t)(t - 1) * Bn + rb + wr0 + r) * 6 + 2];
        }

        // acc = gh partial; a-correction folded into r/z cols only (summed gates)
        ull acc[RPW][6];
        #pragma unroll
        for (int r = 0; r < RPW; r++) {
            ull a0p = pk2(af[r].x, af[r].x);
            ull a1p = pk2(af[r].y, af[r].y);
            #pragma unroll
            for (int c = 0; c < 4; c++) {
                acc[r][c] = mul2(a0p, w56[c]);
                fma2(acc[r][c], a1p, w57[c]);
            }
            acc[r][4] = 0ULL; acc[r][5] = 0ULL;
        }

        // acc += h @ W_hh^T  (warp's 8 rows, thread's 12 cols)
        const float* hb = &hs[wr0 * SH];
        #pragma unroll 2
        for (int k2 = 0; k2 < 64; k2++) {
            float2 hv[RPW];
            #pragma unroll
            for (int r = 0; r < RPW; r++)
                hv[r] = *(const float2*)(hb + r * SH + 2 * k2);
            const float* wrow = &Wt[(2 * k2) * SWT + jc];
            ull wA[6], wB[6];
            #pragma unroll
            for (int c = 0; c < 6; c++) {
                wA[c] = *(const ull*)(wrow + 64 * c);
                wB[c] = *(const ull*)(wrow + SWT + 64 * c);
            }
            #pragma unroll
            for (int r = 0; r < RPW; r++) {
                ull hx = pk2(hv[r].x, hv[r].x);
                ull hy = pk2(hv[r].y, hv[r].y);
                #pragma unroll
                for (int c = 0; c < 6; c++) {
                    fma2(acc[r][c], hx, wA[c]);
                    fma2(acc[r][c], hy, wB[c]);
                }
            }
        }

        // gates
        #pragma unroll
        for (int r = 0; r < RPW; r++) {
            const float* gp = &g_sc[(size_t)(rb + wr0 + r) * NC + jc];
            ull a0p = pk2(af[r].x, af[r].x);
            ull a1p = pk2(af[r].y, af[r].y);
            #pragma unroll
            for (int p = 0; p < 2; p++) {
                float2 gir = *(const float2*)(gp + 64 * p);
                float2 giz = *(const float2*)(gp + 128 + 64 * p);
                float2 gin = *(const float2*)(gp + 256 + 64 * p);
                ull anc = mul2(a0p, w56[p + 4]);   // a-corr for n-cols: input side
                fma2(anc, a1p, w57[p + 4]);
                float2 an  = up2(anc);
                float2 ghr = up2(acc[r][p]);
                float2 ghz = up2(acc[r][p + 2]);
                float2 ghn = up2(acc[r][p + 4]);
                float2 bh  = up2(bhn[p]);
                float rgx = sigf(gir.x + ghr.x), rgy = sigf(gir.y + ghr.y);
                float zgx = sigf(giz.x + ghz.x), zgy = sigf(giz.y + ghz.y);
                float nx = tanha(gin.x + an.x + rgx * (ghn.x + bh.x));
                float ny = tanha(gin.y + an.y + rgy * (ghn.y + bh.y));
                float2 ho = up2(hold[r][p]);
                float hxn = (1.f - zgx) * nx + zgx * ho.x;
                float hyn = (1.f - zgy) * ny + zgy * ho.y;
                hold[r][p] = pk2(hxn, hyn);
                *(float2*)&hs[(wr0 + r) * SH + jc + 64 * p] = make_float2(hxn, hyn);
            }
        }
        __syncwarp();

        // mu / std: lane -> (row = tx>>2, out = tx&3); out 0,1 = mu, 2,3 = std
        float s0 = 0.f, s1 = 0.f;
        const float* hp = &hs[(wr0 + mrow) * SH];
        #pragma unroll 8
        for (int k2 = 0; k2 < 64; k2++) {
            float2 h2 = *(const float2*)(hp + 2 * k2);
            float2 w2 = *(const float2*)(wv + 2 * k2);
            s0 = fmaf(h2.x, w2.x, s0);
            s1 = fmaf(h2.y, w2.y, s1);
        }
        float sv = s0 + s1 + mb;
        out[obase + (size_t)t * Bn * 2] = (mo < 2) ? sv : __expf(0.5f * sv);
        __syncwarp();
    }
}

extern "C" void kernel_launch(void* const* d_in, const int* in_sizes, int n_in,
                              void* d_out, int out_size) {
    const float* lobs  = (const float*)d_in[0];
    const float* enc   = (const float*)d_in[1];
    const float* zin   = (const float*)d_in[2];
    const float* sg    = (const float*)d_in[3];
    const float* fut   = (const float*)d_in[4];
    const float* W_dh  = (const float*)d_in[5];
    const float* b_dh  = (const float*)d_in[6];
    const float* W_vel = (const float*)d_in[7];
    const float* b_vel = (const float*)d_in[8];
    const float* W_ih  = (const float*)d_in[9];
    const float* b_ih  = (const float*)d_in[10];
    const float* W_hh  = (const float*)d_in[11];
    const float* b_hh  = (const float*)d_in[12];
    const float* W_mu  = (const float*)d_in[13];
    const float* b_mu  = (const float*)d_in[14];
    const float* W_std = (const float*)d_in[15];
    const float* b_std = (const float*)d_in[16];
    float* out = (float*)d_out;

    phase1<<<dim3(4, 128), 256>>>(enc, zin, W_ih, b_ih, W_dh, b_dh, b_hh, lobs, sg);

    int smem = (128 * SWT + 64 * SH) * 4;
    cudaFuncSetAttribute(phase2, cudaFuncAttributeMaxDynamicSharedMemorySize, smem);
    phase2<<<256, 256, smem>>>(W_hh, W_ih, b_hh, W_mu, b_mu, W_std, b_std,
                               lobs, W_vel, b_vel, fut, out);
}

// round 5
// speedup vs baseline: 1.6004x; 1.5982x over previous
#include <cuda_runtime.h>
#include <cuda_bf16.h>
#include <cstdint>

typedef unsigned long long ull;
#define Bn 16384
#define Tn 24
#define KZX 1056
#define INd 1060
#define G3  384
#define NC  512
#define WS  136

__device__ __align__(16) float g_sc[(size_t)Bn * NC];

__device__ __forceinline__ ull pk2(float x, float y){ ull r; asm("mov.b64 %0,{%1,%2};":"=l"(r):"f"(x),"f"(y)); return r; }
__device__ __forceinline__ float2 up2(ull v){ float2 r; asm("mov.b64 {%0,%1},%2;":"=f"(r.x),"=f"(r.y):"l"(v)); return r; }
__device__ __forceinline__ void fma2(ull &d, ull a, ull b){ asm("fma.rn.f32x2 %0,%1,%2,%0;":"+l"(d):"l"(a),"l"(b)); }
__device__ __forceinline__ float sigf(float x){ return __fdividef(1.f, 1.f + __expf(-x)); }
__device__ __forceinline__ float tanha(float x){ return __fdividef(2.f, 1.f + __expf(-2.f*x)) - 1.f; }
__device__ __forceinline__ uint32_t s2u(const void* p){ uint32_t a; asm("{.reg .u64 t; cvta.to.shared.u64 t,%1; cvt.u32.u64 %0,t;}":"=r"(a):"l"(p)); return a; }
// d = {hi=y, lo=x} as bf16x2
__device__ __forceinline__ uint32_t pkbf(float x, float y){ uint32_t d; asm("cvt.rn.bf16x2.f32 %0,%1,%2;":"=r"(d):"f"(y),"f"(x)); return d; }
__device__ __forceinline__ float blo(uint32_t v){ return __uint_as_float(v<<16); }
__device__ __forceinline__ float bhi(uint32_t v){ return __uint_as_float(v&0xffff0000u); }
__device__ __forceinline__ void mmabf(float* c, const uint32_t* a, uint32_t b0, uint32_t b1){
    asm("mma.sync.aligned.m16n8k16.row.col.f32.bf16.bf16.f32 {%0,%1,%2,%3},{%4,%5,%6,%7},{%8,%9},{%0,%1,%2,%3};"
        : "+f"(c[0]),"+f"(c[1]),"+f"(c[2]),"+f"(c[3])
        : "r"(a[0]),"r"(a[1]),"r"(a[2]),"r"(a[3]),"r"(b0),"r"(b1));
}
__device__ __forceinline__ void ldsm4(uint32_t* r, uint32_t a){
    asm volatile("ldmatrix.sync.aligned.m8n8.x4.shared.b16 {%0,%1,%2,%3},[%4];"
        :"=r"(r[0]),"=r"(r[1]),"=r"(r[2]),"=r"(r[3]):"r"(a));
}

// ---------------- Phase 1 (unchanged, known-good) ----------------
__global__ __launch_bounds__(256,2) void phase1(
    const float* __restrict__ enc, const float* __restrict__ zin,
    const float* __restrict__ W_ih, const float* __restrict__ b_ih,
    const float* __restrict__ W_dh, const float* __restrict__ b_dh,
    const float* __restrict__ b_hh,
    const float* __restrict__ lobs, const float* __restrict__ sg)
{
    __shared__ __align__(16) float As[8][132];
    __shared__ __align__(16) float Bs[8][132];
    __shared__ float colb[128], c58[128], c59[128];
    int tid=threadIdx.x, m0=blockIdx.y*128, n0=blockIdx.x*128;
    int lrow=tid>>1, lkq=(tid&1)*4, ti=(tid>>4)*8, tj=(tid&15)*8;
    ull acc[8][4];
    #pragma unroll
    for(int i=0;i<8;i++){ acc[i][0]=acc[i][1]=acc[i][2]=acc[i][3]=0ULL; }
    int am=m0+lrow, bj=n0+lrow;
    const float* brow=(bj<G3)?(W_ih+(size_t)bj*INd):(W_dh+(size_t)(bj-G3)*KZX);
    const float* ae=enc+(size_t)am*1024; const float* az=zin+(size_t)am*32;
    for(int k0=0;k0<KZX;k0+=8){
        int kk=k0+lkq;
        float4 av=(kk<1024)?*(const float4*)(ae+kk):*(const float4*)(az+(kk-1024));
        As[lkq][lrow]=av.x; As[lkq+1][lrow]=av.y; As[lkq+2][lrow]=av.z; As[lkq+3][lrow]=av.w;
        float4 bv=*(const float4*)(brow+kk);
        Bs[lkq][lrow]=bv.x; Bs[lkq+1][lrow]=bv.y; Bs[lkq+2][lrow]=bv.z; Bs[lkq+3][lrow]=bv.w;
        __syncthreads();
        #pragma unroll
        for(int k=0;k<8;k++){
            float a[8];
            *(float4*)&a[0]=*(const float4*)&As[k][ti];
            *(float4*)&a[4]=*(const float4*)&As[k][ti+4];
            ull bp[4];
            #pragma unroll
            for(int c=0;c<4;c++) bp[c]=*(const ull*)&Bs[k][tj+2*c];
            #pragma unroll
            for(int i=0;i<8;i++){ ull ap=pk2(a[i],a[i]);
                #pragma unroll
                for(int c=0;c<4;c++) fma2(acc[i][c],ap,bp[c]); }
        }
        __syncthreads();
    }
    bool gi=(n0<G3);
    if(tid<128){ int j=n0+tid;
        if(gi){ colb[tid]=b_ih[j]+((n0<256)?b_hh[j]:0.f);
                c58[tid]=W_ih[(size_t)j*INd+1058]; c59[tid]=W_ih[(size_t)j*INd+1059]; }
        else  { colb[tid]=b_dh[j-G3]; c58[tid]=0.f; c59[tid]=0.f; } }
    __syncthreads();
    const float idt=1.0f/4.8f;
    #pragma unroll
    for(int i=0;i<8;i++){
        int m=m0+ti+i; float r0=0.f,r1=0.f;
        if(gi){ r0=(sg[m*2]-lobs[m*6])*idt; r1=(sg[m*2+1]-lobs[m*6+1])*idt; }
        #pragma unroll
        for(int c=0;c<4;c++){
            float2 v=up2(acc[i][c]); int jj=tj+2*c;
            v.x+=colb[jj]+r0*c58[jj]+r1*c59[jj];
            v.y+=colb[jj+1]+r0*c58[jj+1]+r1*c59[jj+1];
            *(float2*)&g_sc[(size_t)m*NC+n0+jj]=v;
        }
    }
}

// -------- Phase 2: HMMA (mma.sync bf16 hi/lo) GRU recurrence --------
// smem: WH bf16[384*136] @0 (104448B), WL @104448, wa float2[384] @208896,
//       wm4 float4[128] @211968, bh2 float2[64] @214016. total 214528.
#define SM2 214528
__global__ __launch_bounds__(256,1) void phase2h(
    const float* __restrict__ W_hh, const float* __restrict__ W_ih,
    const float* __restrict__ b_hh,
    const float* __restrict__ W_mu, const float* __restrict__ b_mu,
    const float* __restrict__ W_std, const float* __restrict__ b_std,
    const float* __restrict__ lobs, const float* __restrict__ W_vel,
    const float* __restrict__ b_vel, const float* __restrict__ fut,
    float* __restrict__ out)
{
    extern __shared__ __align__(1024) char sm[];
    __nv_bfloat16* WHs=(__nv_bfloat16*)sm;
    __nv_bfloat16* WLs=(__nv_bfloat16*)(sm+104448);
    float2* was=(float2*)(sm+208896);
    float4* wm4=(float4*)(sm+211968);
    float2* bh2=(float2*)(sm+214016);
    int tid=threadIdx.x, lane=tid&31, wid=tid>>5;
    int q=lane&3, rq=lane>>2;
    int row0=blockIdx.x*128+wid*16+rq, row1=row0+8;

    for(int i=tid;i<G3*128;i+=256){
        int n=i>>7,k=i&127; float w=W_hh[i];
        __nv_bfloat16 hb=__float2bfloat16(w);
        float lf=w-__bfloat162float(hb);
        WHs[n*WS+k]=hb; WLs[n*WS+k]=__float2bfloat16(lf);
    }
    for(int i=tid;i<G3;i+=256)
        was[i]=make_float2(W_ih[(size_t)i*INd+1056],W_ih[(size_t)i*INd+1057]);
    if(tid<128) wm4[tid]=make_float4(W_mu[tid],W_mu[128+tid],W_std[tid],W_std[128+tid]);
    if(tid<64)  bh2[tid]=make_float2(b_hh[256+2*tid],b_hh[257+2*tid]);
    __syncthreads();

    uint32_t sWH=s2u(WHs), sWL=s2u(WLs);
    uint32_t boff=(uint32_t)(((lane&7)*WS+(lane>>3)*8)*2);

    // A (h) fragments, hi/lo bf16, double buffered
    uint32_t Ah[8][4], Al[8][4], Nh[8][4], Nl[8][4];
    #pragma unroll
    for(int kt=0;kt<8;kt++){
        #pragma unroll
        for(int rg=0;rg<4;rg++){
            int r=(rg&1)?row1:row0;
            int cb=kt*16+((rg>>1)*8)+2*q;
            float2 v=*(const float2*)&g_sc[(size_t)r*NC+G3+cb];
            uint32_t hh=pkbf(v.x,v.y);
            Ah[kt][rg]=hh;
            Al[kt][rg]=pkbf(v.x-blo(hh), v.y-bhi(hh));
        }
    }
    float2 a0r0,a0r1;
    { float s0=b_vel[0],s1=b_vel[1],t0=s0,t1=s1;
      #pragma unroll
      for(int k=0;k<6;k++){
          float v0=__ldg(&lobs[row0*6+k]), v1=__ldg(&lobs[row1*6+k]);
          s0=fmaf(v0,W_vel[k],s0); s1=fmaf(v0,W_vel[6+k],s1);
          t0=fmaf(v1,W_vel[k],t0); t1=fmaf(v1,W_vel[6+k],t1); }
      a0r0=make_float2(s0,s1); a0r1=make_float2(t0,t1); }
    float bm0=b_mu[0],bm1=b_mu[1],bs0=b_std[0],bs1=b_std[1];

    for(int t=0;t<Tn;t++){
        float2 aR0,aR1;
        if(t==0){ aR0=a0r0; aR1=a0r1; }
        else { aR0=*(const float2*)&fut[((size_t)(t-1)*Bn+row0)*6+2];
               aR1=*(const float2*)&fut[((size_t)(t-1)*Bn+row1)*6+2]; }
        float p0=0,p1=0,p2=0,p3=0,p4=0,p5=0,p6=0,p7=0;
        #pragma unroll
        for(int c=0;c<16;c++){
            const float* gp0=&g_sc[(size_t)row0*NC+8*c+2*q];
            const float* gp1=&g_sc[(size_t)row1*NC+8*c+2*q];
            float2 gr0=*(const float2*)gp0, gz0=*(const float2*)(gp0+128), gn0=*(const float2*)(gp0+256);
            float2 gr1=*(const float2*)gp1, gz1=*(const float2*)(gp1+128), gn1=*(const float2*)(gp1+256);
            float cr[4]={0,0,0,0}, cz[4]={0,0,0,0}, cn[4]={0,0,0,0};
            #pragma unroll
            for(int k2=0;k2<4;k2++){
                uint32_t ab=(uint32_t)(((8*c)*WS+k2*32)*2)+boff;
                uint32_t br[4],bz[4],bn[4],brl[4],bzl[4],bnl[4];
                ldsm4(br, sWH+ab);               ldsm4(brl,sWL+ab);
                ldsm4(bz, sWH+ab+128*WS*2);      ldsm4(bzl,sWL+ab+128*WS*2);
                ldsm4(bn, sWH+ab+256*WS*2);      ldsm4(bnl,sWL+ab+256*WS*2);
                #pragma unroll
                for(int h2=0;h2<2;h2++){
                    int kt=2*k2+h2;
                    mmabf(cr,Ah[kt],br[2*h2],br[2*h2+1]);
                    mmabf(cz,Ah[kt],bz[2*h2],bz[2*h2+1]);
                    mmabf(cn,Ah[kt],bn[2*h2],bn[2*h2+1]);
                    mmabf(cr,Al[kt],br[2*h2],br[2*h2+1]);
                    mmabf(cz,Al[kt],bz[2*h2],bz[2*h2+1]);
                    mmabf(cn,Al[kt],bn[2*h2],bn[2*h2+1]);
                    mmabf(cr,Ah[kt],brl[2*h2],brl[2*h2+1]);
                    mmabf(cz,Ah[kt],bzl[2*h2],bzl[2*h2+1]);
                    mmabf(cn,Ah[kt],bnl[2*h2],bnl[2*h2+1]);
                }
            }
            float4 wr=*(const float4*)&was[8*c+2*q];
            float4 wz=*(const float4*)&was[128+8*c+2*q];
            float4 wn=*(const float4*)&was[256+8*c+2*q];
            float2 bh=bh2[4*c+q];
            float4 w0=wm4[8*c+2*q], w1=wm4[8*c+2*q+1];
            int kt=c>>1, co=(c&1)*2;
            float hp0x=blo(Ah[kt][co])+blo(Al[kt][co]);
            float hp0y=bhi(Ah[kt][co])+bhi(Al[kt][co]);
            float hp1x=blo(Ah[kt][co+1])+blo(Al[kt][co+1]);
            float hp1y=bhi(Ah[kt][co+1])+bhi(Al[kt][co+1]);
            float r0x=sigf(gr0.x+aR0.x*wr.x+aR0.y*wr.y+cr[0]);
            float r0y=sigf(gr0.y+aR0.x*wr.z+aR0.y*wr.w+cr[1]);
            float r1x=sigf(gr1.x+aR1.x*wr.x+aR1.y*wr.y+cr[2]);
            float r1y=sigf(gr1.y+aR1.x*wr.z+aR1.y*wr.w+cr[3]);
            float z0x=sigf(gz0.x+aR0.x*wz.x+aR0.y*wz.y+cz[0]);
            float z0y=sigf(gz0.y+aR0.x*wz.z+aR0.y*wz.w+cz[1]);
            float z1x=sigf(gz1.x+aR1.x*wz.x+aR1.y*wz.y+cz[2]);
            float z1y=sigf(gz1.y+aR1.x*wz.z+aR1.y*wz.w+cz[3]);
            float n0x=tanha(gn0.x+aR0.x*wn.x+aR0.y*wn.y+r0x*(cn[0]+bh.x));
            float n0y=tanha(gn0.y+aR0.x*wn.z+aR0.y*wn.w+r0y*(cn[1]+bh.y));
            float n1x=tanha(gn1.x+aR1.x*wn.x+aR1.y*wn.y+r1x*(cn[2]+bh.x));
            float n1y=tanha(gn1.y+aR1.x*wn.z+aR1.y*wn.w+r1y*(cn[3]+bh.y));
            float h0x=(1.f-z0x)*n0x+z0x*hp0x;
            float h0y=(1.f-z0y)*n0y+z0y*hp0y;
            float h1x=(1.f-z1x)*n1x+z1x*hp1x;
            float h1y=(1.f-z1y)*n1y+z1y*hp1y;
            p0=fmaf(h0x,w0.x,p0); p0=fmaf(h0y,w1.x,p0);
            p1=fmaf(h0x,w0.y,p1); p1=fmaf(h0y,w1.y,p1);
            p2=fmaf(h0x,w0.z,p2); p2=fmaf(h0y,w1.z,p2);
            p3=fmaf(h0x,w0.w,p3); p3=fmaf(h0y,w1.w,p3);
            p4=fmaf(h1x,w0.x,p4); p4=fmaf(h1y,w1.x,p4);
            p5=fmaf(h1x,w0.y,p5); p5=fmaf(h1y,w1.y,p5);
            p6=fmaf(h1x,w0.z,p6); p6=fmaf(h1y,w1.z,p6);
            p7=fmaf(h1x,w0.w,p7); p7=fmaf(h1y,w1.w,p7);
            uint32_t nh0=pkbf(h0x,h0y);
            Nh[kt][co]=nh0; Nl[kt][co]=pkbf(h0x-blo(nh0), h0y-bhi(nh0));
            uint32_t nh1=pkbf(h1x,h1y);
            Nh[kt][co+1]=nh1; Nl[kt][co+1]=pkbf(h1x-blo(nh1), h1y-bhi(nh1));
        }
        p0+=__shfl_xor_sync(~0u,p0,1); p0+=__shfl_xor_sync(~0u,p0,2);
        p1+=__shfl_xor_sync(~0u,p1,1); p1+=__shfl_xor_sync(~0u,p1,2);
        p2+=__shfl_xor_sync(~0u,p2,1); p2+=__shfl_xor_sync(~0u,p2,2);
        p3+=__shfl_xor_sync(~0u,p3,1); p3+=__shfl_xor_sync(~0u,p3,2);
        p4+=__shfl_xor_sync(~0u,p4,1); p4+=__shfl_xor_sync(~0u,p4,2);
        p5+=__shfl_xor_sync(~0u,p5,1); p5+=__shfl_xor_sync(~0u,p5,2);
        p6+=__shfl_xor_sync(~0u,p6,1); p6+=__shfl_xor_sync(~0u,p6,2);
        p7+=__shfl_xor_sync(~0u,p7,1); p7+=__shfl_xor_sync(~0u,p7,2);
        int orow=(q&1)?row1:row0;
        float2 ov; size_t oa;
        if(q<2){ ov=make_float2(((q&1)?p4:p0)+bm0, ((q&1)?p5:p1)+bm1);
                 oa=(size_t)t*(Bn*2)+(size_t)orow*2; }
        else   { ov=make_float2(__expf(0.5f*(((q&1)?p6:p2)+bs0)),
                                __expf(0.5f*(((q&1)?p7:p3)+bs1)));
                 oa=(size_t)(Tn+t)*(Bn*2)+(size_t)orow*2; }
        *(float2*)&out[oa]=ov;
        #pragma unroll
        for(int kt=0;kt<8;kt++){
            #pragma unroll
            for(int rg=0;rg<4;rg++){ Ah[kt][rg]=Nh[kt][rg]; Al[kt][rg]=Nl[kt][rg]; }
        }
    }
}

extern "C" void kernel_launch(void* const* d_in, const int* in_sizes, int n_in,
                              void* d_out, int out_size) {
    const float* lobs=(const float*)d_in[0];
    const float* enc =(const float*)d_in[1];
    const float* zin =(const float*)d_in[2];
    const float* sg  =(const float*)d_in[3];
    const float* fut =(const float*)d_in[4];
    const float* W_dh=(const float*)d_in[5];
    const float* b_dh=(const float*)d_in[6];
    const float* W_vel=(const float*)d_in[7];
    const float* b_vel=(const float*)d_in[8];
    const float* W_ih=(const float*)d_in[9];
    const float* b_ih=(const float*)d_in[10];
    const float* W_hh=(const float*)d_in[11];
    const float* b_hh=(const float*)d_in[12];
    const float* W_mu=(const float*)d_in[13];
    const float* b_mu=(const float*)d_in[14];
    const float* W_std=(const float*)d_in[15];
    const float* b_std=(const float*)d_in[16];
    float* out=(float*)d_out;

    phase1<<<dim3(4,128),256>>>(enc,zin,W_ih,b_ih,W_dh,b_dh,b_hh,lobs,sg);

    cudaFuncSetAttribute(phase2h, cudaFuncAttributeMaxDynamicSharedMemorySize, SM2);
    phase2h<<<128,256,SM2>>>(W_hh,W_ih,b_hh,W_mu,b_mu,W_std,b_std,
                             lobs,W_vel,b_vel,fut,out);
}

// round 6
// speedup vs baseline: 2.3984x; 1.4986x over previous
#include <cuda_runtime.h>
#include <cuda_bf16.h>
#include <cstdint>

#define Bn 16384
#define Tn 24
#define KZX 1056
#define INd 1060
#define G3  384
#define NC  512
#define WS  136

__device__ __align__(16) float g_sc[(size_t)Bn * NC];

__device__ __forceinline__ float sigf(float x){ return __fdividef(1.f, 1.f + __expf(-x)); }
__device__ __forceinline__ float tanha(float x){ return __fdividef(2.f, 1.f + __expf(-2.f*x)) - 1.f; }
__device__ __forceinline__ uint32_t s2u(const void* p){ uint32_t a; asm("{.reg .u64 t; cvta.to.shared.u64 t,%1; cvt.u32.u64 %0,t;}":"=r"(a):"l"(p)); return a; }
// d = {hi=y, lo=x} as bf16x2
__device__ __forceinline__ uint32_t pkbf(float x, float y){ uint32_t d; asm("cvt.rn.bf16x2.f32 %0,%1,%2;":"=r"(d):"f"(y),"f"(x)); return d; }
__device__ __forceinline__ float blo(uint32_t v){ return __uint_as_float(v<<16); }
__device__ __forceinline__ float bhi(uint32_t v){ return __uint_as_float(v&0xffff0000u); }
__device__ __forceinline__ void mmabf(float* c, const uint32_t* a, uint32_t b0, uint32_t b1){
    asm("mma.sync.aligned.m16n8k16.row.col.f32.bf16.bf16.f32 {%0,%1,%2,%3},{%4,%5,%6,%7},{%8,%9},{%0,%1,%2,%3};"
        : "+f"(c[0]),"+f"(c[1]),"+f"(c[2]),"+f"(c[3])
        : "r"(a[0]),"r"(a[1]),"r"(a[2]),"r"(a[3]),"r"(b0),"r"(b1));
}
__device__ __forceinline__ void ldsm4(uint32_t* r, uint32_t a){
    asm volatile("ldmatrix.sync.aligned.m8n8.x4.shared.b16 {%0,%1,%2,%3},[%4];"
        :"=r"(r[0]),"=r"(r[1]),"=r"(r[2]),"=r"(r[3]):"r"(a));
}

// -------- Phase 1: HMMA bf16 hi/lo GEMM --------
// block tile 128M x 256N, 512 threads (16 warps: 2m x 8n, warp tile 64x32)
// smem: Ah[2][128][24]bf16 @0 (12288B), Al @12288, Bh[2][256][24] @24576 (24576B),
//       Bl @49152, colb @73728, c58 @74752, c59 @75776. total 76800.
#define P1SM 76800
__global__ __launch_bounds__(512,1) void phase1h(
    const float* __restrict__ enc, const float* __restrict__ zin,
    const float* __restrict__ W_ih, const float* __restrict__ b_ih,
    const float* __restrict__ W_dh, const float* __restrict__ b_dh,
    const float* __restrict__ b_hh,
    const float* __restrict__ lobs, const float* __restrict__ sg)
{
    extern __shared__ __align__(1024) char sm[];
    uint32_t sb=s2u(sm);
    const uint32_t oAh=0, oAl=12288, oBh=24576, oBl=49152;
    float* colb=(float*)(sm+73728); float* c58=(float*)(sm+74752); float* c59=(float*)(sm+75776);
    int tid=threadIdx.x, lane=tid&31, w=tid>>5;
    int wm=w>>3, wn=w&7;
    int m0=blockIdx.y*128, n0=blockIdx.x*256;

    if(tid<256){
        int j=n0+tid; float cb,w58=0.f,w59=0.f;
        if(j<G3){ cb=b_ih[j]+((j<256)?b_hh[j]:0.f);
                  w58=W_ih[(size_t)j*INd+1058]; w59=W_ih[(size_t)j*INd+1059]; }
        else cb=b_dh[j-G3];
        colb[tid]=cb; c58[tid]=w58; c59[tid]=w59;
    }

    int ra=tid>>2, kq=(tid&3)*4;
    int ma=m0+ra;
    const float* ae=enc+(size_t)ma*1024; const float* az=zin+(size_t)ma*32;
    int jb0=n0+ra, jb1=jb0+128;
    const float* bp0=(jb0<G3)?(W_ih+(size_t)jb0*INd):(W_dh+(size_t)(jb0-G3)*KZX);
    const float* bp1=(jb1<G3)?(W_ih+(size_t)jb1*INd):(W_dh+(size_t)(jb1-G3)*KZX);

    float acc[4][4][4];
    #pragma unroll
    for(int i=0;i<4;i++)
        #pragma unroll
        for(int j2=0;j2<4;j2++){ acc[i][j2][0]=0.f; acc[i][j2][1]=0.f; acc[i][j2][2]=0.f; acc[i][j2][3]=0.f; }

#define CVST(OH,OL,off,v) { \
    uint32_t _h0=pkbf((v).x,(v).y), _h1=pkbf((v).z,(v).w); \
    float _rx=(v).x-blo(_h0), _ry=(v).y-bhi(_h0), _rz=(v).z-blo(_h1), _rw=(v).w-bhi(_h1); \
    uint32_t _l0=pkbf(_rx,_ry), _l1=pkbf(_rz,_rw); \
    *(uint2*)(sm+(OH)+(off))=make_uint2(_h0,_h1); \
    *(uint2*)(sm+(OL)+(off))=make_uint2(_l0,_l1); }
#define LDT(kt) { int kk=(kt)*16+kq; \
    av=(kk<1024)?*(const float4*)(ae+kk):*(const float4*)(az+(kk-1024)); \
    b0v=*(const float4*)(bp0+kk); b1v=*(const float4*)(bp1+kk); }
#define STT(bf) { \
    CVST(oAh,oAl,(bf)*6144+ra*48+(tid&3)*8, av); \
    CVST(oBh,oBl,(bf)*12288+ra*48+(tid&3)*8, b0v); \
    CVST(oBh,oBl,(bf)*12288+(ra+128)*48+(tid&3)*8, b1v); }

    float4 av,b0v,b1v;
    LDT(0); STT(0);
    __syncthreads();

    for(int kt=0;kt<66;kt++){
        int buf=kt&1;
        if(kt<65) LDT(kt+1);
        uint32_t aBh=sb+oAh+buf*6144+(uint32_t)((wm*64+(lane&15))*48+(lane>>4)*16);
        uint32_t aBl=aBh+(oAl-oAh);
        uint32_t bOff=(uint32_t)((wn*32+(lane>>4)*8+(lane&7))*48+((lane>>3)&1)*16);
        uint32_t bBh=sb+oBh+buf*12288+bOff;
        uint32_t bBl=bBh+(oBl-oBh);
        uint32_t Bh0[4],Bh1[4],Bl0[4],Bl1[4];
        ldsm4(Bh0,bBh); ldsm4(Bh1,bBh+16*48);
        ldsm4(Bl0,bBl); ldsm4(Bl1,bBl+16*48);
        #pragma unroll
        for(int mt=0;mt<4;mt++){
            uint32_t Af[4],Alf[4];
            ldsm4(Af, aBh+(uint32_t)(mt*16*48));
            ldsm4(Alf,aBl+(uint32_t)(mt*16*48));
            #pragma unroll
            for(int nt=0;nt<4;nt++){
                uint32_t b0=(nt<2?Bh0:Bh1)[(nt&1)*2], b1=(nt<2?Bh0:Bh1)[(nt&1)*2+1];
                uint32_t l0=(nt<2?Bl0:Bl1)[(nt&1)*2], l1=(nt<2?Bl0:Bl1)[(nt&1)*2+1];
                mmabf(acc[mt][nt],Af,b0,b1);
                mmabf(acc[mt][nt],Alf,b0,b1);
                mmabf(acc[mt][nt],Af,l0,l1);
            }
        }
        __syncthreads();
        if(kt<65){ int nb=(kt+1)&1; STT(nb); }
        __syncthreads();
    }

    const float idt=1.f/4.8f;
    #pragma unroll
    for(int mt=0;mt<4;mt++){
        #pragma unroll
        for(int h=0;h<2;h++){
            int m=m0+wm*64+mt*16+(lane>>2)+8*h;
            float r0=(sg[2*m]-lobs[6*m])*idt, r1=(sg[2*m+1]-lobs[6*m+1])*idt;
            #pragma unroll
            for(int nt=0;nt<4;nt++){
                int jl=wn*32+nt*8+2*(lane&3);
                float vx=acc[mt][nt][2*h]  +colb[jl]  +r0*c58[jl]  +r1*c59[jl];
                float vy=acc[mt][nt][2*h+1]+colb[jl+1]+r0*c58[jl+1]+r1*c59[jl+1];
                *(float2*)&g_sc[(size_t)m*NC+n0+jl]=make_float2(vx,vy);
            }
        }
    }
#undef CVST
#undef LDT
#undef STT
}

// -------- Phase 2: HMMA (mma.sync bf16 hi/lo) GRU recurrence (unchanged) --------
#define SM2 214528
__global__ __launch_bounds__(256,1) void phase2h(
    const float* __restrict__ W_hh, const float* __restrict__ W_ih,
    const float* __restrict__ b_hh,
    const float* __restrict__ W_mu, const float* __restrict__ b_mu,
    const float* __restrict__ W_std, const float* __restrict__ b_std,
    const float* __restrict__ lobs, const float* __restrict__ W_vel,
    const float* __restrict__ b_vel, const float* __restrict__ fut,
    float* __restrict__ out)
{
    extern __shared__ __align__(1024) char sm[];
    __nv_bfloat16* WHs=(__nv_bfloat16*)sm;
    __nv_bfloat16* WLs=(__nv_bfloat16*)(sm+104448);
    float2* was=(float2*)(sm+208896);
    float4* wm4=(float4*)(sm+211968);
    float2* bh2=(float2*)(sm+214016);
    int tid=threadIdx.x, lane=tid&31, wid=tid>>5;
    int q=lane&3, rq=lane>>2;
    int row0=blockIdx.x*128+wid*16+rq, row1=row0+8;

    for(int i=tid;i<G3*128;i+=256){
        int n=i>>7,k=i&127; float w=W_hh[i];
        __nv_bfloat16 hb=__float2bfloat16(w);
        float lf=w-__bfloat162float(hb);
        WHs[n*WS+k]=hb; WLs[n*WS+k]=__float2bfloat16(lf);
    }
    for(int i=tid;i<G3;i+=256)
        was[i]=make_float2(W_ih[(size_t)i*INd+1056],W_ih[(size_t)i*INd+1057]);
    if(tid<128) wm4[tid]=make_float4(W_mu[tid],W_mu[128+tid],W_std[tid],W_std[128+tid]);
    if(tid<64)  bh2[tid]=make_float2(b_hh[256+2*tid],b_hh[257+2*tid]);
    __syncthreads();

    uint32_t sWH=s2u(WHs), sWL=s2u(WLs);
    uint32_t boff=(uint32_t)(((lane&7)*WS+(lane>>3)*8)*2);

    uint32_t Ah[8][4], Al[8][4], Nh[8][4], Nl[8][4];
    #pragma unroll
    for(int kt=0;kt<8;kt++){
        #pragma unroll
        for(int rg=0;rg<4;rg++){
            int r=(rg&1)?row1:row0;
            int cb=kt*16+((rg>>1)*8)+2*q;
            float2 v=*(const float2*)&g_sc[(size_t)r*NC+G3+cb];
            uint32_t hh=pkbf(v.x,v.y);
            Ah[kt][rg]=hh;
            Al[kt][rg]=pkbf(v.x-blo(hh), v.y-bhi(hh));
        }
    }
    float2 a0r0,a0r1;
    { float s0=b_vel[0],s1=b_vel[1],t0=s0,t1=s1;
      #pragma unroll
      for(int k=0;k<6;k++){
          float v0=__ldg(&lobs[row0*6+k]), v1=__ldg(&lobs[row1*6+k]);
          s0=fmaf(v0,W_vel[k],s0); s1=fmaf(v0,W_vel[6+k],s1);
          t0=fmaf(v1,W_vel[k],t0); t1=fmaf(v1,W_vel[6+k],t1); }
      a0r0=make_float2(s0,s1); a0r1=make_float2(t0,t1); }
    float bm0=b_mu[0],bm1=b_mu[1],bs0=b_std[0],bs1=b_std[1];

    for(int t=0;t<Tn;t++){
        float2 aR0,aR1;
        if(t==0){ aR0=a0r0; aR1=a0r1; }
        else { aR0=*(const float2*)&fut[((size_t)(t-1)*Bn+row0)*6+2];
               aR1=*(const float2*)&fut[((size_t)(t-1)*Bn+row1)*6+2]; }
        float p0=0,p1=0,p2=0,p3=0,p4=0,p5=0,p6=0,p7=0;
        #pragma unroll
        for(int c=0;c<16;c++){
            const float* gp0=&g_sc[(size_t)row0*NC+8*c+2*q];
            const float* gp1=&g_sc[(size_t)row1*NC+8*c+2*q];
            float2 gr0=*(const float2*)gp0, gz0=*(const float2*)(gp0+128), gn0=*(const float2*)(gp0+256);
            float2 gr1=*(const float2*)gp1, gz1=*(const float2*)(gp1+128), gn1=*(const float2*)(gp1+256);
            float cr[4]={0,0,0,0}, cz[4]={0,0,0,0}, cn[4]={0,0,0,0};
            #pragma unroll
            for(int k2=0;k2<4;k2++){
                uint32_t ab=(uint32_t)(((8*c)*WS+k2*32)*2)+boff;
                uint32_t br[4],bz[4],bn[4],brl[4],bzl[4],bnl[4];
                ldsm4(br, sWH+ab);               ldsm4(brl,sWL+ab);
                ldsm4(bz, sWH+ab+128*WS*2);      ldsm4(bzl,sWL+ab+128*WS*2);
                ldsm4(bn, sWH+ab+256*WS*2);      ldsm4(bnl,sWL+ab+256*WS*2);
                #pragma unroll
                for(int h2=0;h2<2;h2++){
                    int kt=2*k2+h2;
                    mmabf(cr,Ah[kt],br[2*h2],br[2*h2+1]);
                    mmabf(cz,Ah[kt],bz[2*h2],bz[2*h2+1]);
                    mmabf(cn,Ah[kt],bn[2*h2],bn[2*h2+1]);
                    mmabf(cr,Al[kt],br[2*h2],br[2*h2+1]);
                    mmabf(cz,Al[kt],bz[2*h2],bz[2*h2+1]);
                    mmabf(cn,Al[kt],bn[2*h2],bn[2*h2+1]);
                    mmabf(cr,Ah[kt],brl[2*h2],brl[2*h2+1]);
                    mmabf(cz,Ah[kt],bzl[2*h2],bzl[2*h2+1]);
                    mmabf(cn,Ah[kt],bnl[2*h2],bnl[2*h2+1]);
                }
            }
            float4 wr=*(const float4*)&was[8*c+2*q];
            float4 wz=*(const float4*)&was[128+8*c+2*q];
            float4 wn=*(const float4*)&was[256+8*c+2*q];
            float2 bh=bh2[4*c+q];
            float4 w0=wm4[8*c+2*q], w1=wm4[8*c+2*q+1];
            int kt=c>>1, co=(c&1)*2;
            float hp0x=blo(Ah[kt][co])+blo(Al[kt][co]);
            float hp0y=bhi(Ah[kt][co])+bhi(Al[kt][co]);
            float hp1x=blo(Ah[kt][co+1])+blo(Al[kt][co+1]);
            float hp1y=bhi(Ah[kt][co+1])+bhi(Al[kt][co+1]);
            float r0x=sigf(gr0.x+aR0.x*wr.x+aR0.y*wr.y+cr[0]);
            float r0y=sigf(gr0.y+aR0.x*wr.z+aR0.y*wr.w+cr[1]);
            float r1x=sigf(gr1.x+aR1.x*wr.x+aR1.y*wr.y+cr[2]);
            float r1y=sigf(gr1.y+aR1.x*wr.z+aR1.y*wr.w+cr[3]);
            float z0x=sigf(gz0.x+aR0.x*wz.x+aR0.y*wz.y+cz[0]);
            float z0y=sigf(gz0.y+aR0.x*wz.z+aR0.y*wz.w+cz[1]);
            float z1x=sigf(gz1.x+aR1.x*wz.x+aR1.y*wz.y+cz[2]);
            float z1y=sigf(gz1.y+aR1.x*wz.z+aR1.y*wz.w+cz[3]);
            float n0x=tanha(gn0.x+aR0.x*wn.x+aR0.y*wn.y+r0x*(cn[0]+bh.x));
            float n0y=tanha(gn0.y+aR0.x*wn.z+aR0.y*wn.w+r0y*(cn[1]+bh.y));
            float n1x=tanha(gn1.x+aR1.x*wn.x+aR1.y*wn.y+r1x*(cn[2]+bh.x));
            float n1y=tanha(gn1.y+aR1.x*wn.z+aR1.y*wn.w+r1y*(cn[3]+bh.y));
            float h0x=(1.f-z0x)*n0x+z0x*hp0x;
            float h0y=(1.f-z0y)*n0y+z0y*hp0y;
            float h1x=(1.f-z1x)*n1x+z1x*hp1x;
            float h1y=(1.f-z1y)*n1y+z1y*hp1y;
            p0=fmaf(h0x,w0.x,p0); p0=fmaf(h0y,w1.x,p0);
            p1=fmaf(h0x,w0.y,p1); p1=fmaf(h0y,w1.y,p1);
            p2=fmaf(h0x,w0.z,p2); p2=fmaf(h0y,w1.z,p2);
            p3=fmaf(h0x,w0.w,p3); p3=fmaf(h0y,w1.w,p3);
            p4=fmaf(h1x,w0.x,p4); p4=fmaf(h1y,w1.x,p4);
            p5=fmaf(h1x,w0.y,p5); p5=fmaf(h1y,w1.y,p5);
            p6=fmaf(h1x,w0.z,p6); p6=fmaf(h1y,w1.z,p6);
            p7=fmaf(h1x,w0.w,p7); p7=fmaf(h1y,w1.w,p7);
            uint32_t nh0=pkbf(h0x,h0y);
            Nh[kt][co]=nh0; Nl[kt][co]=pkbf(h0x-blo(nh0), h0y-bhi(nh0));
            uint32_t nh1=pkbf(h1x,h1y);
            Nh[kt][co+1]=nh1; Nl[kt][co+1]=pkbf(h1x-blo(nh1), h1y-bhi(nh1));
        }
        p0+=__shfl_xor_sync(~0u,p0,1); p0+=__shfl_xor_sync(~0u,p0,2);
        p1+=__shfl_xor_sync(~0u,p1,1); p1+=__shfl_xor_sync(~0u,p1,2);
        p2+=__shfl_xor_sync(~0u,p2,1); p2+=__shfl_xor_sync(~0u,p2,2);
        p3+=__shfl_xor_sync(~0u,p3,1); p3+=__shfl_xor_sync(~0u,p3,2);
        p4+=__shfl_xor_sync(~0u,p4,1); p4+=__shfl_xor_sync(~0u,p4,2);
        p5+=__shfl_xor_sync(~0u,p5,1); p5+=__shfl_xor_sync(~0u,p5,2);
        p6+=__shfl_xor_sync(~0u,p6,1); p6+=__shfl_xor_sync(~0u,p6,2);
        p7+=__shfl_xor_sync(~0u,p7,1); p7+=__shfl_xor_sync(~0u,p7,2);
        int orow=(q&1)?row1:row0;
        float2 ov; size_t oa;
        if(q<2){ ov=make_float2(((q&1)?p4:p0)+bm0, ((q&1)?p5:p1)+bm1);
                 oa=(size_t)t*(Bn*2)+(size_t)orow*2; }
        else   { ov=make_float2(__expf(0.5f*(((q&1)?p6:p2)+bs0)),
                                __expf(0.5f*(((q&1)?p7:p3)+bs1)));
                 oa=(size_t)(Tn+t)*(Bn*2)+(size_t)orow*2; }
        *(float2*)&out[oa]=ov;
        #pragma unroll
        for(int kt=0;kt<8;kt++){
            #pragma unroll
            for(int rg=0;rg<4;rg++){ Ah[kt][rg]=Nh[kt][rg]; Al[kt][rg]=Nl[kt][rg]; }
        }
    }
}

extern "C" void kernel_launch(void* const* d_in, const int* in_sizes, int n_in,
                              void* d_out, int out_size) {
    const float* lobs=(const float*)d_in[0];
    const float* enc =(const float*)d_in[1];
    const float* zin =(const float*)d_in[2];
    const float* sg  =(const float*)d_in[3];
    const float* fut =(const float*)d_in[4];
    const float* W_dh=(const float*)d_in[5];
    const float* b_dh=(const float*)d_in[6];
    const float* W_vel=(const float*)d_in[7];
    const float* b_vel=(const float*)d_in[8];
    const float* W_ih=(const float*)d_in[9];
    const float* b_ih=(const float*)d_in[10];
    const float* W_hh=(const float*)d_in[11];
    const float* b_hh=(const float*)d_in[12];
    const float* W_mu=(const float*)d_in[13];
    const float* b_mu=(const float*)d_in[14];
    const float* W_std=(const float*)d_in[15];
    const float* b_std=(const float*)d_in[16];
    float* out=(float*)d_out;

    cudaFuncSetAttribute(phase1h, cudaFuncAttributeMaxDynamicSharedMemorySize, P1SM);
    phase1h<<<dim3(2,128),512,P1SM>>>(enc,zin,W_ih,b_ih,W_dh,b_dh,b_hh,lobs,sg);

    cudaFuncSetAttribute(phase2h, cudaFuncAttributeMaxDynamicSharedMemorySize, SM2);
    phase2h<<<128,256,SM2>>>(W_hh,W_ih,b_hh,W_mu,b_mu,W_std,b_std,
                             lobs,W_vel,b_vel,fut,out);
}

// round 7
// speedup vs baseline: 2.9290x; 1.2212x over previous
#include <cuda_runtime.h>
#include <cuda_bf16.h>
#include <cuda_fp16.h>
#include <cstdint>

#define Bn 16384
#define Tn 24
#define KZX 1056
#define INd 1060
#define G3  384
#define NC  512
#define WS  136

__device__ __align__(16) float g_sc[(size_t)Bn * NC];

__device__ __forceinline__ float sigf(float x){ return __fdividef(1.f, 1.f + __expf(-x)); }
__device__ __forceinline__ float tanha(float x){ return __fdividef(2.f, 1.f + __expf(-2.f*x)) - 1.f; }
__device__ __forceinline__ uint32_t s2u(const void* p){ uint32_t a; asm("{.reg .u64 t; cvta.to.shared.u64 t,%1; cvt.u32.u64 %0,t;}":"=r"(a):"l"(p)); return a; }
// bf16x2 pack: {hi=y, lo=x}
__device__ __forceinline__ uint32_t pkbf(float x, float y){ uint32_t d; asm("cvt.rn.bf16x2.f32 %0,%1,%2;":"=r"(d):"f"(y),"f"(x)); return d; }
__device__ __forceinline__ float blo(uint32_t v){ return __uint_as_float(v<<16); }
__device__ __forceinline__ float bhi(uint32_t v){ return __uint_as_float(v&0xffff0000u); }
// fp16x2 pack: {hi=y, lo=x}
__device__ __forceinline__ uint32_t pkhf(float x, float y){ uint32_t d; asm("cvt.rn.f16x2.f32 %0,%1,%2;":"=r"(d):"f"(y),"f"(x)); return d; }
__device__ __forceinline__ float hlo(uint32_t v){ float f; asm("{.reg .b16 l,h; mov.b32 {l,h},%1; cvt.f32.f16 %0,l;}":"=f"(f):"r"(v)); return f; }
__device__ __forceinline__ float hhi(uint32_t v){ float f; asm("{.reg .b16 l,h; mov.b32 {l,h},%1; cvt.f32.f16 %0,h;}":"=f"(f):"r"(v)); return f; }

__device__ __forceinline__ void mmabf(float* c, const uint32_t* a, uint32_t b0, uint32_t b1){
    asm("mma.sync.aligned.m16n8k16.row.col.f32.bf16.bf16.f32 {%0,%1,%2,%3},{%4,%5,%6,%7},{%8,%9},{%0,%1,%2,%3};"
        : "+f"(c[0]),"+f"(c[1]),"+f"(c[2]),"+f"(c[3])
        : "r"(a[0]),"r"(a[1]),"r"(a[2]),"r"(a[3]),"r"(b0),"r"(b1));
}
__device__ __forceinline__ void mmahf(float* c, const uint32_t* a, uint32_t b0, uint32_t b1){
    asm("mma.sync.aligned.m16n8k16.row.col.f32.f16.f16.f32 {%0,%1,%2,%3},{%4,%5,%6,%7},{%8,%9},{%0,%1,%2,%3};"
        : "+f"(c[0]),"+f"(c[1]),"+f"(c[2]),"+f"(c[3])
        : "r"(a[0]),"r"(a[1]),"r"(a[2]),"r"(a[3]),"r"(b0),"r"(b1));
}
__device__ __forceinline__ void ldsm4(uint32_t* r, uint32_t a){
    asm volatile("ldmatrix.sync.aligned.m8n8.x4.shared.b16 {%0,%1,%2,%3},[%4];"
        :"=r"(r[0]),"=r"(r[1]),"=r"(r[2]),"=r"(r[3]):"r"(a));
}

// -------- Phase 1: HMMA bf16 hi/lo GEMM (unchanged, known-good) --------
#define P1SM 76800
__global__ __launch_bounds__(512,1) void phase1h(
    const float* __restrict__ enc, const float* __restrict__ zin,
    const float* __restrict__ W_ih, const float* __restrict__ b_ih,
    const float* __restrict__ W_dh, const float* __restrict__ b_dh,
    const float* __restrict__ b_hh,
    const float* __restrict__ lobs, const float* __restrict__ sg)
{
    extern __shared__ __align__(1024) char sm[];
    uint32_t sb=s2u(sm);
    const uint32_t oAh=0, oAl=12288, oBh=24576, oBl=49152;
    float* colb=(float*)(sm+73728); float* c58=(float*)(sm+74752); float* c59=(float*)(sm+75776);
    int tid=threadIdx.x, lane=tid&31, w=tid>>5;
    int wm=w>>3, wn=w&7;
    int m0=blockIdx.y*128, n0=blockIdx.x*256;

    if(tid<256){
        int j=n0+tid; float cb,w58=0.f,w59=0.f;
        if(j<G3){ cb=b_ih[j]+((j<256)?b_hh[j]:0.f);
                  w58=W_ih[(size_t)j*INd+1058]; w59=W_ih[(size_t)j*INd+1059]; }
        else cb=b_dh[j-G3];
        colb[tid]=cb; c58[tid]=w58; c59[tid]=w59;
    }

    int ra=tid>>2, kq=(tid&3)*4;
    int ma=m0+ra;
    const float* ae=enc+(size_t)ma*1024; const float* az=zin+(size_t)ma*32;
    int jb0=n0+ra, jb1=jb0+128;
    const float* bp0=(jb0<G3)?(W_ih+(size_t)jb0*INd):(W_dh+(size_t)(jb0-G3)*KZX);
    const float* bp1=(jb1<G3)?(W_ih+(size_t)jb1*INd):(W_dh+(size_t)(jb1-G3)*KZX);

    float acc[4][4][4];
    #pragma unroll
    for(int i=0;i<4;i++)
        #pragma unroll
        for(int j2=0;j2<4;j2++){ acc[i][j2][0]=0.f; acc[i][j2][1]=0.f; acc[i][j2][2]=0.f; acc[i][j2][3]=0.f; }

#define CVST(OH,OL,off,v) { \
    uint32_t _h0=pkbf((v).x,(v).y), _h1=pkbf((v).z,(v).w); \
    float _rx=(v).x-blo(_h0), _ry=(v).y-bhi(_h0), _rz=(v).z-blo(_h1), _rw=(v).w-bhi(_h1); \
    uint32_t _l0=pkbf(_rx,_ry), _l1=pkbf(_rz,_rw); \
    *(uint2*)(sm+(OH)+(off))=make_uint2(_h0,_h1); \
    *(uint2*)(sm+(OL)+(off))=make_uint2(_l0,_l1); }
#define LDT(kt) { int kk=(kt)*16+kq; \
    av=(kk<1024)?*(const float4*)(ae+kk):*(const float4*)(az+(kk-1024)); \
    b0v=*(const float4*)(bp0+kk); b1v=*(const float4*)(bp1+kk); }
#define STT(bf) { \
    CVST(oAh,oAl,(bf)*6144+ra*48+(tid&3)*8, av); \
    CVST(oBh,oBl,(bf)*12288+ra*48+(tid&3)*8, b0v); \
    CVST(oBh,oBl,(bf)*12288+(ra+128)*48+(tid&3)*8, b1v); }

    float4 av,b0v,b1v;
    LDT(0); STT(0);
    __syncthreads();

    for(int kt=0;kt<66;kt++){
        int buf=kt&1;
        if(kt<65) LDT(kt+1);
        uint32_t aBh=sb+oAh+buf*6144+(uint32_t)((wm*64+(lane&15))*48+(lane>>4)*16);
        uint32_t aBl=aBh+(oAl-oAh);
        uint32_t bOff=(uint32_t)((wn*32+(lane>>4)*8+(lane&7))*48+((lane>>3)&1)*16);
        uint32_t bBh=sb+oBh+buf*12288+bOff;
        uint32_t bBl=bBh+(oBl-oBh);
        uint32_t Bh0[4],Bh1[4],Bl0[4],Bl1[4];
        ldsm4(Bh0,bBh); ldsm4(Bh1,bBh+16*48);
        ldsm4(Bl0,bBl); ldsm4(Bl1,bBl+16*48);
        #pragma unroll
        for(int mt=0;mt<4;mt++){
            uint32_t Af[4],Alf[4];
            ldsm4(Af, aBh+(uint32_t)(mt*16*48));
            ldsm4(Alf,aBl+(uint32_t)(mt*16*48));
            #pragma unroll
            for(int nt=0;nt<4;nt++){
                uint32_t b0=(nt<2?Bh0:Bh1)[(nt&1)*2], b1=(nt<2?Bh0:Bh1)[(nt&1)*2+1];
                uint32_t l0=(nt<2?Bl0:Bl1)[(nt&1)*2], l1=(nt<2?Bl0:Bl1)[(nt&1)*2+1];
                mmabf(acc[mt][nt],Af,b0,b1);
                mmabf(acc[mt][nt],Alf,b0,b1);
                mmabf(acc[mt][nt],Af,l0,l1);
            }
        }
        __syncthreads();
        if(kt<65){ int nb=(kt+1)&1; STT(nb); }
        __syncthreads();
    }

    const float idt=1.f/4.8f;
    #pragma unroll
    for(int mt=0;mt<4;mt++){
        #pragma unroll
        for(int h=0;h<2;h++){
            int m=m0+wm*64+mt*16+(lane>>2)+8*h;
            float r0=(sg[2*m]-lobs[6*m])*idt, r1=(sg[2*m+1]-lobs[6*m+1])*idt;
            #pragma unroll
            for(int nt=0;nt<4;nt++){
                int jl=wn*32+nt*8+2*(lane&3);
                float vx=acc[mt][nt][2*h]  +colb[jl]  +r0*c58[jl]  +r1*c59[jl];
                float vy=acc[mt][nt][2*h+1]+colb[jl+1]+r0*c58[jl+1]+r1*c59[jl+1];
                *(float2*)&g_sc[(size_t)m*NC+n0+jl]=make_float2(vx,vy);
            }
        }
    }
#undef CVST
#undef LDT
#undef STT
}

// -------- Phase 2: HMMA fp16 (W single, h hi/lo, 2-product) GRU recurrence --------
// 147 blocks x 224 threads (7 warps x 16 rows = 112 rows/block)
// smem: WHs fp16[384*136] @0 (104448B), was float2[384] @104448 (3072B),
//       wm4 float4[128] @107520 (2048B), bh2 float2[64] @109568 (512B). total 110080.
#define SM2 110080
#define RPB 112
__global__ __launch_bounds__(224,1) void phase2h(
    const float* __restrict__ W_hh, const float* __restrict__ W_ih,
    const float* __restrict__ b_hh,
    const float* __restrict__ W_mu, const float* __restrict__ b_mu,
    const float* __restrict__ W_std, const float* __restrict__ b_std,
    const float* __restrict__ lobs, const float* __restrict__ W_vel,
    const float* __restrict__ b_vel, const float* __restrict__ fut,
    float* __restrict__ out)
{
    extern __shared__ __align__(1024) char sm[];
    __half* WHs=(__half*)sm;
    float2* was=(float2*)(sm+104448);
    float4* wm4=(float4*)(sm+107520);
    float2* bh2=(float2*)(sm+109568);
    int tid=threadIdx.x, lane=tid&31, wid=tid>>5;
    int q=lane&3, rq=lane>>2;
    int rb=blockIdx.x*RPB;
    int row0=rb+wid*16+rq, row1=row0+8;
    bool active=(rb+wid*16)<Bn;

    for(int i=tid;i<G3*128;i+=224){
        int n=i>>7,k=i&127;
        WHs[n*WS+k]=__float2half(W_hh[i]);
    }
    for(int i=tid;i<G3;i+=224)
        was[i]=make_float2(W_ih[(size_t)i*INd+1056],W_ih[(size_t)i*INd+1057]);
    if(tid<128) wm4[tid]=make_float4(W_mu[tid],W_mu[128+tid],W_std[tid],W_std[128+tid]);
    if(tid<64)  bh2[tid]=make_float2(b_hh[256+2*tid],b_hh[257+2*tid]);
    __syncthreads();
    if(!active) return;

    uint32_t sWH=s2u(WHs);
    uint32_t boff=(uint32_t)(((lane&7)*WS+(lane>>3)*8)*2);

    uint32_t Ah[8][4], Al[8][4], Nh[8][4], Nl[8][4];
    #pragma unroll
    for(int kt=0;kt<8;kt++){
        #pragma unroll
        for(int rg=0;rg<4;rg++){
            int r=(rg&1)?row1:row0;
            int cb=kt*16+((rg>>1)*8)+2*q;
            float2 v=*(const float2*)&g_sc[(size_t)r*NC+G3+cb];
            uint32_t hh=pkhf(v.x,v.y);
            Ah[kt][rg]=hh;
            Al[kt][rg]=pkhf(v.x-hlo(hh), v.y-hhi(hh));
        }
    }
    float2 a0r0,a0r1;
    { float s0=b_vel[0],s1=b_vel[1],t0=s0,t1=s1;
      #pragma unroll
      for(int k=0;k<6;k++){
          float v0=__ldg(&lobs[row0*6+k]), v1=__ldg(&lobs[row1*6+k]);
          s0=fmaf(v0,W_vel[k],s0); s1=fmaf(v0,W_vel[6+k],s1);
          t0=fmaf(v1,W_vel[k],t0); t1=fmaf(v1,W_vel[6+k],t1); }
      a0r0=make_float2(s0,s1); a0r1=make_float2(t0,t1); }
    float bm0=b_mu[0],bm1=b_mu[1],bs0=b_std[0],bs1=b_std[1];

    for(int t=0;t<Tn;t++){
        float2 aR0,aR1;
        if(t==0){ aR0=a0r0; aR1=a0r1; }
        else { aR0=*(const float2*)&fut[((size_t)(t-1)*Bn+row0)*6+2];
               aR1=*(const float2*)&fut[((size_t)(t-1)*Bn+row1)*6+2]; }
        float p0=0,p1=0,p2=0,p3=0,p4=0,p5=0,p6=0,p7=0;
        #pragma unroll
        for(int c=0;c<16;c++){
            const float* gp0=&g_sc[(size_t)row0*NC+8*c+2*q];
            const float* gp1=&g_sc[(size_t)row1*NC+8*c+2*q];
            float2 gr0=*(const float2*)gp0, gz0=*(const float2*)(gp0+128), gn0=*(const float2*)(gp0+256);
            float2 gr1=*(const float2*)gp1, gz1=*(const float2*)(gp1+128), gn1=*(const float2*)(gp1+256);
            float cr[4]={0,0,0,0}, cz[4]={0,0,0,0}, cn[4]={0,0,0,0};
            #pragma unroll
            for(int k2=0;k2<4;k2++){
                uint32_t ab=(uint32_t)(((8*c)*WS+k2*32)*2)+boff;
                uint32_t br[4],bz[4],bn[4];
                ldsm4(br, sWH+ab);
                ldsm4(bz, sWH+ab+128*WS*2);
                ldsm4(bn, sWH+ab+256*WS*2);
                #pragma unroll
                for(int h2=0;h2<2;h2++){
                    int kt=2*k2+h2;
                    mmahf(cr,Ah[kt],br[2*h2],br[2*h2+1]);
                    mmahf(cr,Al[kt],br[2*h2],br[2*h2+1]);
                    mmahf(cz,Ah[kt],bz[2*h2],bz[2*h2+1]);
                    mmahf(cz,Al[kt],bz[2*h2],bz[2*h2+1]);
                    mmahf(cn,Ah[kt],bn[2*h2],bn[2*h2+1]);
                    mmahf(cn,Al[kt],bn[2*h2],bn[2*h2+1]);
                }
            }
            float4 wr=*(const float4*)&was[8*c+2*q];
            float4 wz=*(const float4*)&was[128+8*c+2*q];
            float4 wn=*(const float4*)&was[256+8*c+2*q];
            float2 bh=bh2[4*c+q];
            float4 w0=wm4[8*c+2*q], w1=wm4[8*c+2*q+1];
            int kt=c>>1, co=(c&1)*2;
            float hp0x=hlo(Ah[kt][co])+hlo(Al[kt][co]);
            float hp0y=hhi(Ah[kt][co])+hhi(Al[kt][co]);
            float hp1x=hlo(Ah[kt][co+1])+hlo(Al[kt][co+1]);
            float hp1y=hhi(Ah[kt][co+1])+hhi(Al[kt][co+1]);
            float r0x=sigf(gr0.x+aR0.x*wr.x+aR0.y*wr.y+cr[0]);
            float r0y=sigf(gr0.y+aR0.x*wr.z+aR0.y*wr.w+cr[1]);
            float r1x=sigf(gr1.x+aR1.x*wr.x+aR1.y*wr.y+cr[2]);
            float r1y=sigf(gr1.y+aR1.x*wr.z+aR1.y*wr.w+cr[3]);
            float z0x=sigf(gz0.x+aR0.x*wz.x+aR0.y*wz.y+cz[0]);
            float z0y=sigf(gz0.y+aR0.x*wz.z+aR0.y*wz.w+cz[1]);
            float z1x=sigf(gz1.x+aR1.x*wz.x+aR1.y*wz.y+cz[2]);
            float z1y=sigf(gz1.y+aR1.x*wz.z+aR1.y*wz.w+cz[3]);
            float n0x=tanha(gn0.x+aR0.x*wn.x+aR0.y*wn.y+r0x*(cn[0]+bh.x));
            float n0y=tanha(gn0.y+aR0.x*wn.z+aR0.y*wn.w+r0y*(cn[1]+bh.y));
            float n1x=tanha(gn1.x+aR1.x*wn.x+aR1.y*wn.y+r1x*(cn[2]+bh.x));
            float n1y=tanha(gn1.y+aR1.x*wn.z+aR1.y*wn.w+r1y*(cn[3]+bh.y));
            float h0x=(1.f-z0x)*n0x+z0x*hp0x;
            float h0y=(1.f-z0y)*n0y+z0y*hp0y;
            float h1x=(1.f-z1x)*n1x+z1x*hp1x;
            float h1y=(1.f-z1y)*n1y+z1y*hp1y;
            p0=fmaf(h0x,w0.x,p0); p0=fmaf(h0y,w1.x,p0);
            p1=fmaf(h0x,w0.y,p1); p1=fmaf(h0y,w1.y,p1);
            p2=fmaf(h0x,w0.z,p2); p2=fmaf(h0y,w1.z,p2);
            p3=fmaf(h0x,w0.w,p3); p3=fmaf(h0y,w1.w,p3);
            p4=fmaf(h1x,w0.x,p4); p4=fmaf(h1y,w1.x,p4);
            p5=fmaf(h1x,w0.y,p5); p5=fmaf(h1y,w1.y,p5);
            p6=fmaf(h1x,w0.z,p6); p6=fmaf(h1y,w1.z,p6);
            p7=fmaf(h1x,w0.w,p7); p7=fmaf(h1y,w1.w,p7);
            uint32_t nh0=pkhf(h0x,h0y);
            Nh[kt][co]=nh0; Nl[kt][co]=pkhf(h0x-hlo(nh0), h0y-hhi(nh0));
            uint32_t nh1=pkhf(h1x,h1y);
            Nh[kt][co+1]=nh1; Nl[kt][co+1]=pkhf(h1x-hlo(nh1), h1y-hhi(nh1));
        }
        p0+=__shfl_xor_sync(~0u,p0,1); p0+=__shfl_xor_sync(~0u,p0,2);
        p1+=__shfl_xor_sync(~0u,p1,1); p1+=__shfl_xor_sync(~0u,p1,2);
        p2+=__shfl_xor_sync(~0u,p2,1); p2+=__shfl_xor_sync(~0u,p2,2);
        p3+=__shfl_xor_sync(~0u,p3,1); p3+=__shfl_xor_sync(~0u,p3,2);
        p4+=__shfl_xor_sync(~0u,p4,1); p4+=__shfl_xor_sync(~0u,p4,2);
        p5+=__shfl_xor_sync(~0u,p5,1); p5+=__shfl_xor_sync(~0u,p5,2);
        p6+=__shfl_xor_sync(~0u,p6,1); p6+=__shfl_xor_sync(~0u,p6,2);
        p7+=__shfl_xor_sync(~0u,p7,1); p7+=__shfl_xor_sync(~0u,p7,2);
        int orow=(q&1)?row1:row0;
        float2 ov; size_t oa;
        if(q<2){ ov=make_float2(((q&1)?p4:p0)+bm0, ((q&1)?p5:p1)+bm1);
                 oa=(size_t)t*(Bn*2)+(size_t)orow*2; }
        else   { ov=make_float2(__expf(0.5f*(((q&1)?p6:p2)+bs0)),
                                __expf(0.5f*(((q&1)?p7:p3)+bs1)));
                 oa=(size_t)(Tn+t)*(Bn*2)+(size_t)orow*2; }
        *(float2*)&out[oa]=ov;
        #pragma unroll
        for(int kt=0;kt<8;kt++){
            #pragma unroll
            for(int rg=0;rg<4;rg++){ Ah[kt][rg]=Nh[kt][rg]; Al[kt][rg]=Nl[kt][rg]; }
        }
    }
}

extern "C" void kernel_launch(void* const* d_in, const int* in_sizes, int n_in,
                              void* d_out, int out_size) {
    const float* lobs=(const float*)d_in[0];
    const float* enc =(const float*)d_in[1];
    const float* zin =(const float*)d_in[2];
    const float* sg  =(const float*)d_in[3];
    const float* fut =(const float*)d_in[4];
    const float* W_dh=(const float*)d_in[5];
    const float* b_dh=(const float*)d_in[6];
    const float* W_vel=(const float*)d_in[7];
    const float* b_vel=(const float*)d_in[8];
    const float* W_ih=(const float*)d_in[9];
    const float* b_ih=(const float*)d_in[10];
    const float* W_hh=(const float*)d_in[11];
    const float* b_hh=(const float*)d_in[12];
    const float* W_mu=(const float*)d_in[13];
    const float* b_mu=(const float*)d_in[14];
    const float* W_std=(const float*)d_in[15];
    const float* b_std=(const float*)d_in[16];
    float* out=(float*)d_out;

    cudaFuncSetAttribute(phase1h, cudaFuncAttributeMaxDynamicSharedMemorySize, P1SM);
    phase1h<<<dim3(2,128),512,P1SM>>>(enc,zin,W_ih,b_ih,W_dh,b_dh,b_hh,lobs,sg);

    cudaFuncSetAttribute(phase2h, cudaFuncAttributeMaxDynamicSharedMemorySize, SM2);
    phase2h<<<147,224,SM2>>>(W_hh,W_ih,b_hh,W_mu,b_mu,W_std,b_std,
                             lobs,W_vel,b_vel,fut,out);
}

// round 9
// speedup vs baseline: 3.1645x; 1.0804x over previous
#include <cuda_runtime.h>
#include <cuda_bf16.h>
#include <cuda_fp16.h>
#include <cstdint>

#define Bn 16384
#define Tn 24
#define KZX 1056
#define INd 1060
#define G3  384
#define NC  512
#define WS  136

__device__ __align__(16) float g_sc[(size_t)Bn * NC];

__device__ __forceinline__ float sigf(float x){ return __fdividef(1.f, 1.f + __expf(-x)); }
__device__ __forceinline__ float tanha(float x){ return __fdividef(2.f, 1.f + __expf(-2.f*x)) - 1.f; }
__device__ __forceinline__ uint32_t s2u(const void* p){ uint32_t a; asm("{.reg .u64 t; cvta.to.shared.u64 t,%1; cvt.u32.u64 %0,t;}":"=r"(a):"l"(p)); return a; }
__device__ __forceinline__ uint32_t pkbf(float x, float y){ uint32_t d; asm("cvt.rn.bf16x2.f32 %0,%1,%2;":"=r"(d):"f"(y),"f"(x)); return d; }
__device__ __forceinline__ float blo(uint32_t v){ return __uint_as_float(v<<16); }
__device__ __forceinline__ float bhi(uint32_t v){ return __uint_as_float(v&0xffff0000u); }
__device__ __forceinline__ uint32_t pkhf(float x, float y){ uint32_t d; asm("cvt.rn.f16x2.f32 %0,%1,%2;":"=r"(d):"f"(y),"f"(x)); return d; }
__device__ __forceinline__ float hlo(uint32_t v){ float f; asm("{.reg .b16 l,h; mov.b32 {l,h},%1; cvt.f32.f16 %0,l;}":"=f"(f):"r"(v)); return f; }
__device__ __forceinline__ float hhi(uint32_t v){ float f; asm("{.reg .b16 l,h; mov.b32 {l,h},%1; cvt.f32.f16 %0,h;}":"=f"(f):"r"(v)); return f; }

__device__ __forceinline__ void mmabf(float* c, const uint32_t* a, uint32_t b0, uint32_t b1){
    asm("mma.sync.aligned.m16n8k16.row.col.f32.bf16.bf16.f32 {%0,%1,%2,%3},{%4,%5,%6,%7},{%8,%9},{%0,%1,%2,%3};"
        : "+f"(c[0]),"+f"(c[1]),"+f"(c[2]),"+f"(c[3])
        : "r"(a[0]),"r"(a[1]),"r"(a[2]),"r"(a[3]),"r"(b0),"r"(b1));
}
__device__ __forceinline__ void mmahf(float* c, const uint32_t* a, uint32_t b0, uint32_t b1){
    asm("mma.sync.aligned.m16n8k16.row.col.f32.f16.f16.f32 {%0,%1,%2,%3},{%4,%5,%6,%7},{%8,%9},{%0,%1,%2,%3};"
        : "+f"(c[0]),"+f"(c[1]),"+f"(c[2]),"+f"(c[3])
        : "r"(a[0]),"r"(a[1]),"r"(a[2]),"r"(a[3]),"r"(b0),"r"(b1));
}
__device__ __forceinline__ void ldsm4(uint32_t* r, uint32_t a){
    asm volatile("ldmatrix.sync.aligned.m8n8.x4.shared.b16 {%0,%1,%2,%3},[%4];"
        :"=r"(r[0]),"=r"(r[1]),"=r"(r[2]),"=r"(r[3]):"r"(a));
}

// -------- Phase 1: HMMA bf16 hi/lo GEMM (unchanged, known-good) --------
#define P1SM 76800
__global__ __launch_bounds__(512,1) void phase1h(
    const float* __restrict__ enc, const float* __restrict__ zin,
    const float* __restrict__ W_ih, const float* __restrict__ b_ih,
    const float* __restrict__ W_dh, const float* __restrict__ b_dh,
    const float* __restrict__ b_hh,
    const float* __restrict__ lobs, const float* __restrict__ sg)
{
    extern __shared__ __align__(1024) char sm[];
    uint32_t sb=s2u(sm);
    const uint32_t oAh=0, oAl=12288, oBh=24576, oBl=49152;
    float* colb=(float*)(sm+73728); float* c58=(float*)(sm+74752); float* c59=(float*)(sm+75776);
    int tid=threadIdx.x, lane=tid&31, w=tid>>5;
    int wm=w>>3, wn=w&7;
    int m0=blockIdx.y*128, n0=blockIdx.x*256;

    if(tid<256){
        int j=n0+tid; float cb,w58=0.f,w59=0.f;
        if(j<G3){ cb=b_ih[j]+((j<256)?b_hh[j]:0.f);
                  w58=W_ih[(size_t)j*INd+1058]; w59=W_ih[(size_t)j*INd+1059]; }
        else cb=b_dh[j-G3];
        colb[tid]=cb; c58[tid]=w58; c59[tid]=w59;
    }

    int ra=tid>>2, kq=(tid&3)*4;
    int ma=m0+ra;
    const float* ae=enc+(size_t)ma*1024; const float* az=zin+(size_t)ma*32;
    int jb0=n0+ra, jb1=jb0+128;
    const float* bp0=(jb0<G3)?(W_ih+(size_t)jb0*INd):(W_dh+(size_t)(jb0-G3)*KZX);
    const float* bp1=(jb1<G3)?(W_ih+(size_t)jb1*INd):(W_dh+(size_t)(jb1-G3)*KZX);

    float acc[4][4][4];
    #pragma unroll
    for(int i=0;i<4;i++)
        #pragma unroll
        for(int j2=0;j2<4;j2++){ acc[i][j2][0]=0.f; acc[i][j2][1]=0.f; acc[i][j2][2]=0.f; acc[i][j2][3]=0.f; }

#define CVST(OH,OL,off,v) { \
    uint32_t _h0=pkbf((v).x,(v).y), _h1=pkbf((v).z,(v).w); \
    float _rx=(v).x-blo(_h0), _ry=(v).y-bhi(_h0), _rz=(v).z-blo(_h1), _rw=(v).w-bhi(_h1); \
    uint32_t _l0=pkbf(_rx,_ry), _l1=pkbf(_rz,_rw); \
    *(uint2*)(sm+(OH)+(off))=make_uint2(_h0,_h1); \
    *(uint2*)(sm+(OL)+(off))=make_uint2(_l0,_l1); }
#define LDT(kt) { int kk=(kt)*16+kq; \
    av=(kk<1024)?*(const float4*)(ae+kk):*(const float4*)(az+(kk-1024)); \
    b0v=*(const float4*)(bp0+kk); b1v=*(const float4*)(bp1+kk); }
#define STT(bf) { \
    CVST(oAh,oAl,(bf)*6144+ra*48+(tid&3)*8, av); \
    CVST(oBh,oBl,(bf)*12288+ra*48+(tid&3)*8, b0v); \
    CVST(oBh,oBl,(bf)*12288+(ra+128)*48+(tid&3)*8, b1v); }

    float4 av,b0v,b1v;
    LDT(0); STT(0);
    __syncthreads();

    for(int kt=0;kt<66;kt++){
        int buf=kt&1;
        if(kt<65) LDT(kt+1);
        uint32_t aBh=sb+oAh+buf*6144+(uint32_t)((wm*64+(lane&15))*48+(lane>>4)*16);
        uint32_t aBl=aBh+(oAl-oAh);
        uint32_t bOff=(uint32_t)((wn*32+(lane>>4)*8+(lane&7))*48+((lane>>3)&1)*16);
        uint32_t bBh=sb+oBh+buf*12288+bOff;
        uint32_t bBl=bBh+(oBl-oBh);
        uint32_t Bh0[4],Bh1[4],Bl0[4],Bl1[4];
        ldsm4(Bh0,bBh); ldsm4(Bh1,bBh+16*48);
        ldsm4(Bl0,bBl); ldsm4(Bl1,bBl+16*48);
        #pragma unroll
        for(int mt=0;mt<4;mt++){
            uint32_t Af[4],Alf[4];
            ldsm4(Af, aBh+(uint32_t)(mt*16*48));
            ldsm4(Alf,aBl+(uint32_t)(mt*16*48));
            #pragma unroll
            for(int nt=0;nt<4;nt++){
                uint32_t b0=(nt<2?Bh0:Bh1)[(nt&1)*2], b1=(nt<2?Bh0:Bh1)[(nt&1)*2+1];
                uint32_t l0=(nt<2?Bl0:Bl1)[(nt&1)*2], l1=(nt<2?Bl0:Bl1)[(nt&1)*2+1];
                mmabf(acc[mt][nt],Af,b0,b1);
                mmabf(acc[mt][nt],Alf,b0,b1);
                mmabf(acc[mt][nt],Af,l0,l1);
            }
        }
        __syncthreads();
        if(kt<65){ int nb=(kt+1)&1; STT(nb); }
        __syncthreads();
    }

    const float idt=1.f/4.8f;
    #pragma unroll
    for(int mt=0;mt<4;mt++){
        #pragma unroll
        for(int h=0;h<2;h++){
            int m=m0+wm*64+mt*16+(lane>>2)+8*h;
            float r0=(sg[2*m]-lobs[6*m])*idt, r1=(sg[2*m+1]-lobs[6*m+1])*idt;
            #pragma unroll
            for(int nt=0;nt<4;nt++){
                int jl=wn*32+nt*8+2*(lane&3);
                float vx=acc[mt][nt][2*h]  +colb[jl]  +r0*c58[jl]  +r1*c59[jl];
                float vy=acc[mt][nt][2*h+1]+colb[jl+1]+r0*c58[jl+1]+r1*c59[jl+1];
                *(float2*)&g_sc[(size_t)m*NC+n0+jl]=make_float2(vx,vy);
            }
        }
    }
#undef CVST
#undef LDT
#undef STT
}

// -------- Phase 2: warp-pair split HMMA fp16 GRU recurrence (fixed hx layout) ----
// 147 blocks x 448 threads (14 warps = 7 pairs x 16 rows = 112 rows/block).
// Each warp-half computes gate cols [64h,64h+64) of r,z,n.
// h exchange: single-buffered smem, per-pair 2 planes(hi/lo) x 16 rows x stride 68 u32.
// Two named barriers per step (write -> bar -> read -> bar).
// smem: WHs fp16[384*136] @0 (104448), was @104448 (3072), wm4 @107520 (2048),
//       bh2 @109568 (512), hx u32[7][2][16][68] @110080 (60928),
//       px float2[7][64] @171008 (3584). total 174592.
#define SM2P 174592
__global__ __launch_bounds__(448,1) void phase2p(
    const float* __restrict__ W_hh, const float* __restrict__ W_ih,
    const float* __restrict__ b_hh,
    const float* __restrict__ W_mu, const float* __restrict__ b_mu,
    const float* __restrict__ W_std, const float* __restrict__ b_std,
    const float* __restrict__ lobs, const float* __restrict__ W_vel,
    const float* __restrict__ b_vel, const float* __restrict__ fut,
    float* __restrict__ out)
{
    extern __shared__ __align__(1024) char sm[];
    __half* WHs=(__half*)sm;
    float2* was=(float2*)(sm+104448);
    float4* wm4=(float4*)(sm+107520);
    float2* bh2=(float2*)(sm+109568);
    uint32_t* hx=(uint32_t*)(sm+110080);
    float2* px=(float2*)(sm+171008);
    int tid=threadIdx.x, lane=tid&31, wid=tid>>5;
    int pair=wid>>1, half=wid&1;
    int q=lane&3, rq=lane>>2;
    int rb=blockIdx.x*112+pair*16;
    int row0=rb+rq, row1=row0+8;
    bool active=rb<Bn;

    for(int i=tid;i<G3*128;i+=448){
        int n=i>>7,k=i&127;
        WHs[n*WS+k]=__float2half(W_hh[i]);
    }
    for(int i=tid;i<G3;i+=448)
        was[i]=make_float2(W_ih[(size_t)i*INd+1056],W_ih[(size_t)i*INd+1057]);
    if(tid<128) wm4[tid]=make_float4(W_mu[tid],W_mu[128+tid],W_std[tid],W_std[128+tid]);
    if(tid<64)  bh2[tid]=make_float2(b_hh[256+2*tid],b_hh[257+2*tid]);
    __syncthreads();
    if(!active) return;

    uint32_t sWH=s2u(WHs);
    uint32_t boff=(uint32_t)(((lane&7)*WS+(lane>>3)*8)*2);
    uint32_t hb=(uint32_t)(pair*2176);   // 2 planes * 16 rows * 68

    uint32_t Ah[8][4], Al[8][4];
    #pragma unroll
    for(int kt=0;kt<8;kt++){
        #pragma unroll
        for(int rg=0;rg<4;rg++){
            int r=(rg&1)?row1:row0;
            int cb=kt*16+((rg>>1)*8)+2*q;
            float2 v=*(const float2*)&g_sc[(size_t)r*NC+G3+cb];
            uint32_t hh=pkhf(v.x,v.y);
            Ah[kt][rg]=hh;
            Al[kt][rg]=pkhf(v.x-hlo(hh), v.y-hhi(hh));
        }
    }
    float2 a0r0,a0r1;
    { float s0=b_vel[0],s1=b_vel[1],t0=s0,t1=s1;
      #pragma unroll
      for(int k=0;k<6;k++){
          float v0=__ldg(&lobs[row0*6+k]), v1=__ldg(&lobs[row1*6+k]);
          s0=fmaf(v0,W_vel[k],s0); s1=fmaf(v0,W_vel[6+k],s1);
          t0=fmaf(v1,W_vel[k],t0); t1=fmaf(v1,W_vel[6+k],t1); }
      a0r0=make_float2(s0,s1); a0r1=make_float2(t0,t1); }
    float bm0=b_mu[0],bm1=b_mu[1],bs0=b_std[0],bs1=b_std[1];

    for(int t=0;t<Tn;t++){
        float2 aR0,aR1;
        if(t==0){ aR0=a0r0; aR1=a0r1; }
        else { aR0=*(const float2*)&fut[((size_t)(t-1)*Bn+row0)*6+2];
               aR1=*(const float2*)&fut[((size_t)(t-1)*Bn+row1)*6+2]; }
        float p0=0,p1=0,p2=0,p3=0,p4=0,p5=0,p6=0,p7=0;
        #pragma unroll
        for(int c2=0;c2<8;c2++){
            int cg=half*8+c2;
            const float* gp0=&g_sc[(size_t)row0*NC+8*cg+2*q];
            const float* gp1=&g_sc[(size_t)row1*NC+8*cg+2*q];
            float2 gr0=*(const float2*)gp0, gz0=*(const float2*)(gp0+128), gn0=*(const float2*)(gp0+256);
            float2 gr1=*(const float2*)gp1, gz1=*(const float2*)(gp1+128), gn1=*(const float2*)(gp1+256);
            float cr[4]={0,0,0,0}, cz[4]={0,0,0,0}, cn[4]={0,0,0,0};
            #pragma unroll
            for(int k2=0;k2<4;k2++){
                uint32_t ab=(uint32_t)(((8*cg)*WS+k2*32)*2)+boff;
                uint32_t br[4],bz[4],bn[4];
                ldsm4(br, sWH+ab);
                ldsm4(bz, sWH+ab+128*WS*2);
                ldsm4(bn, sWH+ab+256*WS*2);
                #pragma unroll
                for(int h2=0;h2<2;h2++){
                    int kt=2*k2+h2;
                    mmahf(cr,Ah[kt],br[2*h2],br[2*h2+1]);
                    mmahf(cr,Al[kt],br[2*h2],br[2*h2+1]);
                    mmahf(cz,Ah[kt],bz[2*h2],bz[2*h2+1]);
                    mmahf(cz,Al[kt],bz[2*h2],bz[2*h2+1]);
                    mmahf(cn,Ah[kt],bn[2*h2],bn[2*h2+1]);
                    mmahf(cn,Al[kt],bn[2*h2],bn[2*h2+1]);
                }
            }
            float4 wr=*(const float4*)&was[8*cg+2*q];
            float4 wz=*(const float4*)&was[128+8*cg+2*q];
            float4 wn=*(const float4*)&was[256+8*cg+2*q];
            float2 bh=bh2[4*cg+q];
            float4 w0=wm4[8*cg+2*q], w1=wm4[8*cg+2*q+1];
            int kt=cg>>1, co=(cg&1)*2;
            float hp0x=hlo(Ah[kt][co])+hlo(Al[kt][co]);
            float hp0y=hhi(Ah[kt][co])+hhi(Al[kt][co]);
            float hp1x=hlo(Ah[kt][co+1])+hlo(Al[kt][co+1]);
            float hp1y=hhi(Ah[kt][co+1])+hhi(Al[kt][co+1]);
            float r0x=sigf(gr0.x+aR0.x*wr.x+aR0.y*wr.y+cr[0]);
            float r0y=sigf(gr0.y+aR0.x*wr.z+aR0.y*wr.w+cr[1]);
            float r1x=sigf(gr1.x+aR1.x*wr.x+aR1.y*wr.y+cr[2]);
            float r1y=sigf(gr1.y+aR1.x*wr.z+aR1.y*wr.w+cr[3]);
            float z0x=sigf(gz0.x+aR0.x*wz.x+aR0.y*wz.y+cz[0]);
            float z0y=sigf(gz0.y+aR0.x*wz.z+aR0.y*wz.w+cz[1]);
            float z1x=sigf(gz1.x+aR1.x*wz.x+aR1.y*wz.y+cz[2]);
            float z1y=sigf(gz1.y+aR1.x*wz.z+aR1.y*wz.w+cz[3]);
            float n0x=tanha(gn0.x+aR0.x*wn.x+aR0.y*wn.y+r0x*(cn[0]+bh.x));
            float n0y=tanha(gn0.y+aR0.x*wn.z+aR0.y*wn.w+r0y*(cn[1]+bh.y));
            float n1x=tanha(gn1.x+aR1.x*wn.x+aR1.y*wn.y+r1x*(cn[2]+bh.x));
            float n1y=tanha(gn1.y+aR1.x*wn.z+aR1.y*wn.w+r1y*(cn[3]+bh.y));
            float h0x=(1.f-z0x)*n0x+z0x*hp0x;
            float h0y=(1.f-z0y)*n0y+z0y*hp0y;
            float h1x=(1.f-z1x)*n1x+z1x*hp1x;
            float h1y=(1.f-z1y)*n1y+z1y*hp1y;
            p0=fmaf(h0x,w0.x,p0); p0=fmaf(h0y,w1.x,p0);
            p1=fmaf(h0x,w0.y,p1); p1=fmaf(h0y,w1.y,p1);
            p2=fmaf(h0x,w0.z,p2); p2=fmaf(h0y,w1.z,p2);
            p3=fmaf(h0x,w0.w,p3); p3=fmaf(h0y,w1.w,p3);
            p4=fmaf(h1x,w0.x,p4); p4=fmaf(h1y,w1.x,p4);
            p5=fmaf(h1x,w0.y,p5); p5=fmaf(h1y,w1.y,p5);
            p6=fmaf(h1x,w0.z,p6); p6=fmaf(h1y,w1.z,p6);
            p7=fmaf(h1x,w0.w,p7); p7=fmaf(h1y,w1.w,p7);
            uint32_t nh0=pkhf(h0x,h0y);
            uint32_t nl0=pkhf(h0x-hlo(nh0), h0y-hhi(nh0));
            uint32_t nh1=pkhf(h1x,h1y);
            uint32_t nl1=pkhf(h1x-hlo(nh1), h1y-hhi(nh1));
            uint32_t wofs=hb+(uint32_t)(cg*4+q);
            hx[wofs+rq*68]          =nh0;
            hx[wofs+(rq+8)*68]      =nh1;
            hx[wofs+1088+rq*68]     =nl0;
            hx[wofs+1088+(rq+8)*68] =nl1;
        }
        p0+=__shfl_xor_sync(~0u,p0,1); p0+=__shfl_xor_sync(~0u,p0,2);
        p1+=__shfl_xor_sync(~0u,p1,1); p1+=__shfl_xor_sync(~0u,p1,2);
        p2+=__shfl_xor_sync(~0u,p2,1); p2+=__shfl_xor_sync(~0u,p2,2);
        p3+=__shfl_xor_sync(~0u,p3,1); p3+=__shfl_xor_sync(~0u,p3,2);
        p4+=__shfl_xor_sync(~0u,p4,1); p4+=__shfl_xor_sync(~0u,p4,2);
        p5+=__shfl_xor_sync(~0u,p5,1); p5+=__shfl_xor_sync(~0u,p5,2);
        p6+=__shfl_xor_sync(~0u,p6,1); p6+=__shfl_xor_sync(~0u,p6,2);
        p7+=__shfl_xor_sync(~0u,p7,1); p7+=__shfl_xor_sync(~0u,p7,2);
        float2 mine;
        if(q<2) mine=make_float2((q&1)?p4:p0,(q&1)?p5:p1);
        else    mine=make_float2((q&1)?p6:p2,(q&1)?p7:p3);
        px[pair*64+half*32+lane]=mine;
        asm volatile("bar.sync %0,64;"::"r"(pair+1):"memory");
        #pragma unroll
        for(int kt=0;kt<8;kt++){
            #pragma unroll
            for(int ch=0;ch<2;ch++){
                uint32_t pw=hb+(uint32_t)((2*kt+ch)*4+q);
                Ah[kt][ch*2  ]=hx[pw+rq*68];
                Ah[kt][ch*2+1]=hx[pw+(rq+8)*68];
                Al[kt][ch*2  ]=hx[pw+1088+rq*68];
                Al[kt][ch*2+1]=hx[pw+1088+(rq+8)*68];
            }
        }
        if(half==0){
            float2 other=px[pair*64+32+lane];
            float vx=mine.x+other.x, vy=mine.y+other.y;
            int orow=(q&1)?row1:row0;
            if(q<2)
                *(float2*)&out[(size_t)t*Bn*2+(size_t)orow*2]=make_float2(vx+bm0,vy+bm1);
            else
                *(float2*)&out[(size_t)(Tn+t)*Bn*2+(size_t)orow*2]=
                    make_float2(__expf(0.5f*(vx+bs0)),__expf(0.5f*(vy+bs1)));
        }
        asm volatile("bar.sync %0,64;"::"r"(pair+1):"memory");
    }
}

extern "C" void kernel_launch(void* const* d_in, const int* in_sizes, int n_in,
                              void* d_out, int out_size) {
    const float* lobs=(const float*)d_in[0];
    const float* enc =(const float*)d_in[1];
    const float* zin =(const float*)d_in[2];
    const float* sg  =(const float*)d_in[3];
    const float* fut =(const float*)d_in[4];
    const float* W_dh=(const float*)d_in[5];
    const float* b_dh=(const float*)d_in[6];
    const float* W_vel=(const float*)d_in[7];
    const float* b_vel=(const float*)d_in[8];
    const float* W_ih=(const float*)d_in[9];
    const float* b_ih=(const float*)d_in[10];
    const float* W_hh=(const float*)d_in[11];
    const float* b_hh=(const float*)d_in[12];
    const float* W_mu=(const float*)d_in[13];
    const float* b_mu=(const float*)d_in[14];
    const float* W_std=(const float*)d_in[15];
    const float* b_std=(const float*)d_in[16];
    float* out=(float*)d_out;

    cudaFuncSetAttribute(phase1h, cudaFuncAttributeMaxDynamicSharedMemorySize, P1SM);
    phase1h<<<dim3(2,128),512,P1SM>>>(enc,zin,W_ih,b_ih,W_dh,b_dh,b_hh,lobs,sg);

    cudaFuncSetAttribute(phase2p, cudaFuncAttributeMaxDynamicSharedMemorySize, SM2P);
    phase2p<<<147,448,SM2P>>>(W_hh,W_ih,b_hh,W_mu,b_mu,W_std,b_std,
                              lobs,W_vel,b_vel,fut,out);
}

// round 10
// speedup vs baseline: 3.3820x; 1.0687x over previous
#include <cuda_runtime.h>
#include <cuda_bf16.h>
#include <cuda_fp16.h>
#include <cstdint>

#define Bn 16384
#define Tn 24
#define KZX 1056
#define INd 1060
#define G3  384
#define NC  512
#define WS  136

__device__ __align__(16) float g_sc[(size_t)Bn * NC];

__device__ __forceinline__ float sigf(float x){ return __fdividef(1.f, 1.f + __expf(-x)); }
__device__ __forceinline__ float tanha(float x){ return __fdividef(2.f, 1.f + __expf(-2.f*x)) - 1.f; }
__device__ __forceinline__ uint32_t s2u(const void* p){ uint32_t a; asm("{.reg .u64 t; cvta.to.shared.u64 t,%1; cvt.u32.u64 %0,t;}":"=r"(a):"l"(p)); return a; }
__device__ __forceinline__ uint32_t pkbf(float x, float y){ uint32_t d; asm("cvt.rn.bf16x2.f32 %0,%1,%2;":"=r"(d):"f"(y),"f"(x)); return d; }
__device__ __forceinline__ float blo(uint32_t v){ return __uint_as_float(v<<16); }
__device__ __forceinline__ float bhi(uint32_t v){ return __uint_as_float(v&0xffff0000u); }
__device__ __forceinline__ uint32_t pkhf(float x, float y){ uint32_t d; asm("cvt.rn.f16x2.f32 %0,%1,%2;":"=r"(d):"f"(y),"f"(x)); return d; }
__device__ __forceinline__ void mmabf(float* c, const uint32_t* a, uint32_t b0, uint32_t b1){
    asm("mma.sync.aligned.m16n8k16.row.col.f32.bf16.bf16.f32 {%0,%1,%2,%3},{%4,%5,%6,%7},{%8,%9},{%0,%1,%2,%3};"
        : "+f"(c[0]),"+f"(c[1]),"+f"(c[2]),"+f"(c[3])
        : "r"(a[0]),"r"(a[1]),"r"(a[2]),"r"(a[3]),"r"(b0),"r"(b1));
}
__device__ __forceinline__ void mmahf(float* c, const uint32_t* a, uint32_t b0, uint32_t b1){
    asm("mma.sync.aligned.m16n8k16.row.col.f32.f16.f16.f32 {%0,%1,%2,%3},{%4,%5,%6,%7},{%8,%9},{%0,%1,%2,%3};"
        : "+f"(c[0]),"+f"(c[1]),"+f"(c[2]),"+f"(c[3])
        : "r"(a[0]),"r"(a[1]),"r"(a[2]),"r"(a[3]),"r"(b0),"r"(b1));
}
__device__ __forceinline__ void ldsm4(uint32_t* r, uint32_t a){
    asm volatile("ldmatrix.sync.aligned.m8n8.x4.shared.b16 {%0,%1,%2,%3},[%4];"
        :"=r"(r[0]),"=r"(r[1]),"=r"(r[2]),"=r"(r[3]):"r"(a));
}

// -------- Phase 1: HMMA bf16 hi/lo GEMM (unchanged, known-good) --------
#define P1SM 76800
__global__ __launch_bounds__(512,1) void phase1h(
    const float* __restrict__ enc, const float* __restrict__ zin,
    const float* __restrict__ W_ih, const float* __restrict__ b_ih,
    const float* __restrict__ W_dh, const float* __restrict__ b_dh,
    const float* __restrict__ b_hh,
    const float* __restrict__ lobs, const float* __restrict__ sg)
{
    extern __shared__ __align__(1024) char sm[];
    uint32_t sb=s2u(sm);
    const uint32_t oAh=0, oAl=12288, oBh=24576, oBl=49152;
    float* colb=(float*)(sm+73728); float* c58=(float*)(sm+74752); float* c59=(float*)(sm+75776);
    int tid=threadIdx.x, lane=tid&31, w=tid>>5;
    int wm=w>>3, wn=w&7;
    int m0=blockIdx.y*128, n0=blockIdx.x*256;

    if(tid<256){
        int j=n0+tid; float cb,w58=0.f,w59=0.f;
        if(j<G3){ cb=b_ih[j]+((j<256)?b_hh[j]:0.f);
                  w58=W_ih[(size_t)j*INd+1058]; w59=W_ih[(size_t)j*INd+1059]; }
        else cb=b_dh[j-G3];
        colb[tid]=cb; c58[tid]=w58; c59[tid]=w59;
    }

    int ra=tid>>2, kq=(tid&3)*4;
    int ma=m0+ra;
    const float* ae=enc+(size_t)ma*1024; const float* az=zin+(size_t)ma*32;
    int jb0=n0+ra, jb1=jb0+128;
    const float* bp0=(jb0<G3)?(W_ih+(size_t)jb0*INd):(W_dh+(size_t)(jb0-G3)*KZX);
    const float* bp1=(jb1<G3)?(W_ih+(size_t)jb1*INd):(W_dh+(size_t)(jb1-G3)*KZX);

    float acc[4][4][4];
    #pragma unroll
    for(int i=0;i<4;i++)
        #pragma unroll
        for(int j2=0;j2<4;j2++){ acc[i][j2][0]=0.f; acc[i][j2][1]=0.f; acc[i][j2][2]=0.f; acc[i][j2][3]=0.f; }

#define CVST(OH,OL,off,v) { \
    uint32_t _h0=pkbf((v).x,(v).y), _h1=pkbf((v).z,(v).w); \
    float _rx=(v).x-blo(_h0), _ry=(v).y-bhi(_h0), _rz=(v).z-blo(_h1), _rw=(v).w-bhi(_h1); \
    uint32_t _l0=pkbf(_rx,_ry), _l1=pkbf(_rz,_rw); \
    *(uint2*)(sm+(OH)+(off))=make_uint2(_h0,_h1); \
    *(uint2*)(sm+(OL)+(off))=make_uint2(_l0,_l1); }
#define LDT(kt) { int kk=(kt)*16+kq; \
    av=(kk<1024)?*(const float4*)(ae+kk):*(const float4*)(az+(kk-1024)); \
    b0v=*(const float4*)(bp0+kk); b1v=*(const float4*)(bp1+kk); }
#define STT(bf) { \
    CVST(oAh,oAl,(bf)*6144+ra*48+(tid&3)*8, av); \
    CVST(oBh,oBl,(bf)*12288+ra*48+(tid&3)*8, b0v); \
    CVST(oBh,oBl,(bf)*12288+(ra+128)*48+(tid&3)*8, b1v); }

    float4 av,b0v,b1v;
    LDT(0); STT(0);
    __syncthreads();

    for(int kt=0;kt<66;kt++){
        int buf=kt&1;
        if(kt<65) LDT(kt+1);
        uint32_t aBh=sb+oAh+buf*6144+(uint32_t)((wm*64+(lane&15))*48+(lane>>4)*16);
        uint32_t aBl=aBh+(oAl-oAh);
        uint32_t bOff=(uint32_t)((wn*32+(lane>>4)*8+(lane&7))*48+((lane>>3)&1)*16);
        uint32_t bBh=sb+oBh+buf*12288+bOff;
        uint32_t bBl=bBh+(oBl-oBh);
        uint32_t Bh0[4],Bh1[4],Bl0[4],Bl1[4];
        ldsm4(Bh0,bBh); ldsm4(Bh1,bBh+16*48);
        ldsm4(Bl0,bBl); ldsm4(Bl1,bBl+16*48);
        #pragma unroll
        for(int mt=0;mt<4;mt++){
            uint32_t Af[4],Alf[4];
            ldsm4(Af, aBh+(uint32_t)(mt*16*48));
            ldsm4(Alf,aBl+(uint32_t)(mt*16*48));
            #pragma unroll
            for(int nt=0;nt<4;nt++){
                uint32_t b0=(nt<2?Bh0:Bh1)[(nt&1)*2], b1=(nt<2?Bh0:Bh1)[(nt&1)*2+1];
                uint32_t l0=(nt<2?Bl0:Bl1)[(nt&1)*2], l1=(nt<2?Bl0:Bl1)[(nt&1)*2+1];
                mmabf(acc[mt][nt],Af,b0,b1);
                mmabf(acc[mt][nt],Alf,b0,b1);
                mmabf(acc[mt][nt],Af,l0,l1);
            }
        }
        __syncthreads();
        if(kt<65){ int nb=(kt+1)&1; STT(nb); }
        __syncthreads();
    }

    const float idt=1.f/4.8f;
    #pragma unroll
    for(int mt=0;mt<4;mt++){
        #pragma unroll
        for(int h=0;h<2;h++){
            int m=m0+wm*64+mt*16+(lane>>2)+8*h;
            float r0=(sg[2*m]-lobs[6*m])*idt, r1=(sg[2*m+1]-lobs[6*m+1])*idt;
            #pragma unroll
            for(int nt=0;nt<4;nt++){
                int jl=wn*32+nt*8+2*(lane&3);
                float vx=acc[mt][nt][2*h]  +colb[jl]  +r0*c58[jl]  +r1*c59[jl];
                float vy=acc[mt][nt][2*h+1]+colb[jl+1]+r0*c58[jl+1]+r1*c59[jl+1];
                *(float2*)&g_sc[(size_t)m*NC+n0+jl]=make_float2(vx,vy);
            }
        }
    }
#undef CVST
#undef LDT
#undef STT
}

// -------- Phase 2: 32-rows/warp, single-product fp16, fp32 h-state in regs ----
// 147 blocks x 256 threads (8 warps): groups g=0..2 double (tiles 2g,2g+1, 32
// rows, 2 warps split N-halves), group 3 single (tile 6). 112 rows/block.
// smem: WHs fp16[384*136] @0 (104448), was @104448 (3072), wm4 @107520 (2048),
//       bh2 @109568 (512), hx u32[7][16][68] @110080 (30464), px @140544 (3584).
#define SM2Q 144128
__global__ __launch_bounds__(256,1) void phase2q(
    const float* __restrict__ W_hh, const float* __restrict__ W_ih,
    const float* __restrict__ b_hh,
    const float* __restrict__ W_mu, const float* __restrict__ b_mu,
    const float* __restrict__ W_std, const float* __restrict__ b_std,
    const float* __restrict__ lobs, const float* __restrict__ W_vel,
    const float* __restrict__ b_vel, const float* __restrict__ fut,
    float* __restrict__ out)
{
    extern __shared__ __align__(1024) char sm[];
    __half* WHs=(__half*)sm;
    float2* was=(float2*)(sm+104448);
    float4* wm4=(float4*)(sm+107520);
    float2* bh2=(float2*)(sm+109568);
    uint32_t* hx=(uint32_t*)(sm+110080);
    float2* px=(float2*)(sm+140544);
    int tid=threadIdx.x, lane=tid&31, wid=tid>>5;
    int grp=wid>>1, half=wid&1;
    int nt2=(grp<3)?2:1;
    int tb=2*grp;                 // grp 3 -> tile 6
    int q=lane&3, rq=lane>>2;
    int rb=blockIdx.x*112;

    for(int i=tid;i<G3*128;i+=256){
        int n=i>>7,k=i&127;
        WHs[n*WS+k]=__float2half(W_hh[i]);
    }
    for(int i=tid;i<G3;i+=256)
        was[i]=make_float2(W_ih[(size_t)i*INd+1056],W_ih[(size_t)i*INd+1057]);
    if(tid<128) wm4[tid]=make_float4(W_mu[tid],W_mu[128+tid],W_std[tid],W_std[128+tid]);
    if(tid<64)  bh2[tid]=make_float2(b_hh[256+2*tid],b_hh[257+2*tid]);
    __syncthreads();
    if(rb+tb*16>=Bn) return;

    uint32_t sWH=s2u(WHs);
    uint32_t boff=(uint32_t)(((lane&7)*WS+(lane>>3)*8)*2);
    int r0a=rb+tb*16+rq, r1a=r0a+8;

    uint32_t Ah[2][8][4];
    float hp[2][32];
    #pragma unroll
    for(int nt=0;nt<2;nt++) if(nt<nt2){
        int ro=nt*16;
        #pragma unroll
        for(int kt=0;kt<8;kt++){
            #pragma unroll
            for(int rg=0;rg<4;rg++){
                int r=((rg&1)?r1a:r0a)+ro;
                int cb=kt*16+((rg>>1)*8)+2*q;
                float2 v=*(const float2*)&g_sc[(size_t)r*NC+G3+cb];
                Ah[nt][kt][rg]=pkhf(v.x,v.y);
            }
        }
        #pragma unroll
        for(int c2=0;c2<8;c2++){
            int cg=half*8+c2;
            float2 v0=*(const float2*)&g_sc[(size_t)(r0a+ro)*NC+G3+8*cg+2*q];
            float2 v1=*(const float2*)&g_sc[(size_t)(r1a+ro)*NC+G3+8*cg+2*q];
            hp[nt][c2*4+0]=v0.x; hp[nt][c2*4+1]=v0.y;
            hp[nt][c2*4+2]=v1.x; hp[nt][c2*4+3]=v1.y;
        }
    }
    float bm0=b_mu[0],bm1=b_mu[1],bs0=b_std[0],bs1=b_std[1];

    for(int t=0;t<Tn;t++){
        float2 aR0[2],aR1[2];
        if(t==0){
            #pragma unroll
            for(int nt=0;nt<2;nt++) if(nt<nt2){
                int ro=nt*16;
                float s0=b_vel[0],s1=b_vel[1],u0=s0,u1=s1;
                #pragma unroll
                for(int k=0;k<6;k++){
                    float v0=__ldg(&lobs[(r0a+ro)*6+k]), v1=__ldg(&lobs[(r1a+ro)*6+k]);
                    s0=fmaf(v0,W_vel[k],s0); s1=fmaf(v0,W_vel[6+k],s1);
                    u0=fmaf(v1,W_vel[k],u0); u1=fmaf(v1,W_vel[6+k],u1); }
                aR0[nt]=make_float2(s0,s1); aR1[nt]=make_float2(u0,u1);
            }
        } else {
            #pragma unroll
            for(int nt=0;nt<2;nt++) if(nt<nt2){
                int ro=nt*16;
                aR0[nt]=*(const float2*)&fut[((size_t)(t-1)*Bn+r0a+ro)*6+2];
                aR1[nt]=*(const float2*)&fut[((size_t)(t-1)*Bn+r1a+ro)*6+2];
            }
        }
        float p[2][8];
        #pragma unroll
        for(int nt=0;nt<2;nt++)
            #pragma unroll
            for(int i=0;i<8;i++) p[nt][i]=0.f;

        #pragma unroll
        for(int c2=0;c2<8;c2++){
            int cg=half*8+c2;
            float cr[2][4],cz[2][4],cn[2][4];
            #pragma unroll
            for(int nt=0;nt<2;nt++)
                #pragma unroll
                for(int i=0;i<4;i++){ cr[nt][i]=0.f; cz[nt][i]=0.f; cn[nt][i]=0.f; }
            #pragma unroll
            for(int k2=0;k2<4;k2++){
                uint32_t ab=(uint32_t)(((8*cg)*WS+k2*32)*2)+boff;
                uint32_t br[4],bz[4],bn[4];
                ldsm4(br, sWH+ab);
                ldsm4(bz, sWH+ab+128*WS*2);
                ldsm4(bn, sWH+ab+256*WS*2);
                #pragma unroll
                for(int h2=0;h2<2;h2++){
                    int kt=2*k2+h2;
                    #pragma unroll
                    for(int nt=0;nt<2;nt++) if(nt<nt2){
                        mmahf(cr[nt],Ah[nt][kt],br[2*h2],br[2*h2+1]);
                        mmahf(cz[nt],Ah[nt][kt],bz[2*h2],bz[2*h2+1]);
                        mmahf(cn[nt],Ah[nt][kt],bn[2*h2],bn[2*h2+1]);
                    }
                }
            }
            float4 wr=*(const float4*)&was[8*cg+2*q];
            float4 wz=*(const float4*)&was[128+8*cg+2*q];
            float4 wn=*(const float4*)&was[256+8*cg+2*q];
            float2 bh=bh2[4*cg+q];
            float4 w0=wm4[8*cg+2*q], w1=wm4[8*cg+2*q+1];
            #pragma unroll
            for(int nt=0;nt<2;nt++) if(nt<nt2){
                int ro=nt*16;
                const float* gp0=&g_sc[(size_t)(r0a+ro)*NC+8*cg+2*q];
                const float* gp1=&g_sc[(size_t)(r1a+ro)*NC+8*cg+2*q];
                float2 gr0=*(const float2*)gp0, gz0=*(const float2*)(gp0+128), gn0=*(const float2*)(gp0+256);
                float2 gr1=*(const float2*)gp1, gz1=*(const float2*)(gp1+128), gn1=*(const float2*)(gp1+256);
                float r0x=sigf(gr0.x+aR0[nt].x*wr.x+aR0[nt].y*wr.y+cr[nt][0]);
                float r0y=sigf(gr0.y+aR0[nt].x*wr.z+aR0[nt].y*wr.w+cr[nt][1]);
                float r1x=sigf(gr1.x+aR1[nt].x*wr.x+aR1[nt].y*wr.y+cr[nt][2]);
                float r1y=sigf(gr1.y+aR1[nt].x*wr.z+aR1[nt].y*wr.w+cr[nt][3]);
                float z0x=sigf(gz0.x+aR0[nt].x*wz.x+aR0[nt].y*wz.y+cz[nt][0]);
                float z0y=sigf(gz0.y+aR0[nt].x*wz.z+aR0[nt].y*wz.w+cz[nt][1]);
                float z1x=sigf(gz1.x+aR1[nt].x*wz.x+aR1[nt].y*wz.y+cz[nt][2]);
                float z1y=sigf(gz1.y+aR1[nt].x*wz.z+aR1[nt].y*wz.w+cz[nt][3]);
                float n0x=tanha(gn0.x+aR0[nt].x*wn.x+aR0[nt].y*wn.y+r0x*(cn[nt][0]+bh.x));
                float n0y=tanha(gn0.y+aR0[nt].x*wn.z+aR0[nt].y*wn.w+r0y*(cn[nt][1]+bh.y));
                float n1x=tanha(gn1.x+aR1[nt].x*wn.x+aR1[nt].y*wn.y+r1x*(cn[nt][2]+bh.x));
                float n1y=tanha(gn1.y+aR1[nt].x*wn.z+aR1[nt].y*wn.w+r1y*(cn[nt][3]+bh.y));
                float h0x=(1.f-z0x)*n0x+z0x*hp[nt][c2*4+0];
                float h0y=(1.f-z0y)*n0y+z0y*hp[nt][c2*4+1];
                float h1x=(1.f-z1x)*n1x+z1x*hp[nt][c2*4+2];
                float h1y=(1.f-z1y)*n1y+z1y*hp[nt][c2*4+3];
                hp[nt][c2*4+0]=h0x; hp[nt][c2*4+1]=h0y;
                hp[nt][c2*4+2]=h1x; hp[nt][c2*4+3]=h1y;
                p[nt][0]=fmaf(h0x,w0.x,p[nt][0]); p[nt][0]=fmaf(h0y,w1.x,p[nt][0]);
                p[nt][1]=fmaf(h0x,w0.y,p[nt][1]); p[nt][1]=fmaf(h0y,w1.y,p[nt][1]);
                p[nt][2]=fmaf(h0x,w0.z,p[nt][2]); p[nt][2]=fmaf(h0y,w1.z,p[nt][2]);
                p[nt][3]=fmaf(h0x,w0.w,p[nt][3]); p[nt][3]=fmaf(h0y,w1.w,p[nt][3]);
                p[nt][4]=fmaf(h1x,w0.x,p[nt][4]); p[nt][4]=fmaf(h1y,w1.x,p[nt][4]);
                p[nt][5]=fmaf(h1x,w0.y,p[nt][5]); p[nt][5]=fmaf(h1y,w1.y,p[nt][5]);
                p[nt][6]=fmaf(h1x,w0.z,p[nt][6]); p[nt][6]=fmaf(h1y,w1.z,p[nt][6]);
                p[nt][7]=fmaf(h1x,w0.w,p[nt][7]); p[nt][7]=fmaf(h1y,w1.w,p[nt][7]);
                uint32_t nh0=pkhf(h0x,h0y);
                uint32_t nh1=pkhf(h1x,h1y);
                uint32_t wofs=(uint32_t)((tb+nt)*1088+cg*4+q);
                hx[wofs+rq*68]=nh0;
                hx[wofs+(rq+8)*68]=nh1;
            }
        }
        float keepx[2],keepy[2];
        #pragma unroll
        for(int nt=0;nt<2;nt++) if(nt<nt2){
            #pragma unroll
            for(int i=0;i<8;i++){
                p[nt][i]+=__shfl_xor_sync(~0u,p[nt][i],1);
                p[nt][i]+=__shfl_xor_sync(~0u,p[nt][i],2);
            }
            float2 mine;
            if(q<2) mine=make_float2((q&1)?p[nt][4]:p[nt][0],(q&1)?p[nt][5]:p[nt][1]);
            else    mine=make_float2((q&1)?p[nt][6]:p[nt][2],(q&1)?p[nt][7]:p[nt][3]);
            px[(tb+nt)*64+half*32+lane]=mine;
            keepx[nt]=mine.x; keepy[nt]=mine.y;
        }
        asm volatile("bar.sync %0,64;"::"r"(grp+1):"memory");
        #pragma unroll
        for(int nt=0;nt<2;nt++) if(nt<nt2){
            #pragma unroll
            for(int kt=0;kt<8;kt++){
                #pragma unroll
                for(int ch=0;ch<2;ch++){
                    uint32_t pw=(uint32_t)((tb+nt)*1088+(2*kt+ch)*4+q);
                    Ah[nt][kt][ch*2  ]=hx[pw+rq*68];
                    Ah[nt][kt][ch*2+1]=hx[pw+(rq+8)*68];
                }
            }
        }
        if(half==0){
            #pragma unroll
            for(int nt=0;nt<2;nt++) if(nt<nt2){
                float2 other=px[(tb+nt)*64+32+lane];
                float vx=keepx[nt]+other.x, vy=keepy[nt]+other.y;
                int orow=((q&1)?r1a:r0a)+nt*16;
                if(q<2)
                    *(float2*)&out[(size_t)t*Bn*2+(size_t)orow*2]=make_float2(vx+bm0,vy+bm1);
                else
                    *(float2*)&out[(size_t)(Tn+t)*Bn*2+(size_t)orow*2]=
                        make_float2(__expf(0.5f*(vx+bs0)),__expf(0.5f*(vy+bs1)));
            }
        }
        asm volatile("bar.sync %0,64;"::"r"(grp+1):"memory");
    }
}

extern "C" void kernel_launch(void* const* d_in, const int* in_sizes, int n_in,
                              void* d_out, int out_size) {
    const float* lobs=(const float*)d_in[0];
    const float* enc =(const float*)d_in[1];
    const float* zin =(const float*)d_in[2];
    const float* sg  =(const float*)d_in[3];
    const float* fut =(const float*)d_in[4];
    const float* W_dh=(const float*)d_in[5];
    const float* b_dh=(const float*)d_in[6];
    const float* W_vel=(const float*)d_in[7];
    const float* b_vel=(const float*)d_in[8];
    const float* W_ih=(const float*)d_in[9];
    const float* b_ih=(const float*)d_in[10];
    const float* W_hh=(const float*)d_in[11];
    const float* b_hh=(const float*)d_in[12];
    const float* W_mu=(const float*)d_in[13];
    const float* b_mu=(const float*)d_in[14];
    const float* W_std=(const float*)d_in[15];
    const float* b_std=(const float*)d_in[16];
    float* out=(float*)d_out;

    cudaFuncSetAttribute(phase1h, cudaFuncAttributeMaxDynamicSharedMemorySize, P1SM);
    phase1h<<<dim3(2,128),512,P1SM>>>(enc,zin,W_ih,b_ih,W_dh,b_dh,b_hh,lobs,sg);

    cudaFuncSetAttribute(phase2q, cudaFuncAttributeMaxDynamicSharedMemorySize, SM2Q);
    phase2q<<<147,256,SM2Q>>>(W_hh,W_ih,b_hh,W_mu,b_mu,W_std,b_std,
                              lobs,W_vel,b_vel,fut,out);
}

// round 11
// speedup vs baseline: 3.8292x; 1.1322x over previous
#include <cuda_runtime.h>
#include <cuda_bf16.h>
#include <cuda_fp16.h>
#include <cstdint>

#define Bn 16384
#define Tn 24
#define KZX 1056
#define INd 1060
#define G3  384
#define NC  512
#define WS  136

__device__ __align__(16) float g_sc[(size_t)Bn * NC];

__device__ __forceinline__ float sigf(float x){ return __fdividef(1.f, 1.f + __expf(-x)); }
__device__ __forceinline__ float tanha(float x){ return __fdividef(2.f, 1.f + __expf(-2.f*x)) - 1.f; }
__device__ __forceinline__ uint32_t s2u(const void* p){ uint32_t a; asm("{.reg .u64 t; cvta.to.shared.u64 t,%1; cvt.u32.u64 %0,t;}":"=r"(a):"l"(p)); return a; }
__device__ __forceinline__ uint32_t pkbf(float x, float y){ uint32_t d; asm("cvt.rn.bf16x2.f32 %0,%1,%2;":"=r"(d):"f"(y),"f"(x)); return d; }
__device__ __forceinline__ float blo(uint32_t v){ return __uint_as_float(v<<16); }
__device__ __forceinline__ float bhi(uint32_t v){ return __uint_as_float(v&0xffff0000u); }
__device__ __forceinline__ uint32_t pkhf(float x, float y){ uint32_t d; asm("cvt.rn.f16x2.f32 %0,%1,%2;":"=r"(d):"f"(y),"f"(x)); return d; }
__device__ __forceinline__ void mmabf(float* c, const uint32_t* a, uint32_t b0, uint32_t b1){
    asm("mma.sync.aligned.m16n8k16.row.col.f32.bf16.bf16.f32 {%0,%1,%2,%3},{%4,%5,%6,%7},{%8,%9},{%0,%1,%2,%3};"
        : "+f"(c[0]),"+f"(c[1]),"+f"(c[2]),"+f"(c[3])
        : "r"(a[0]),"r"(a[1]),"r"(a[2]),"r"(a[3]),"r"(b0),"r"(b1));
}
__device__ __forceinline__ void mmahf(float* c, const uint32_t* a, uint32_t b0, uint32_t b1){
    asm("mma.sync.aligned.m16n8k16.row.col.f32.f16.f16.f32 {%0,%1,%2,%3},{%4,%5,%6,%7},{%8,%9},{%0,%1,%2,%3};"
        : "+f"(c[0]),"+f"(c[1]),"+f"(c[2]),"+f"(c[3])
        : "r"(a[0]),"r"(a[1]),"r"(a[2]),"r"(a[3]),"r"(b0),"r"(b1));
}
__device__ __forceinline__ void ldsm4(uint32_t* r, uint32_t a){
    asm volatile("ldmatrix.sync.aligned.m8n8.x4.shared.b16 {%0,%1,%2,%3},[%4];"
        :"=r"(r[0]),"=r"(r[1]),"=r"(r[2]),"=r"(r[3]):"r"(a));
}

// -------- Phase 1: HMMA bf16 hi/lo GEMM (unchanged, known-good) --------
#define P1SM 76800
__global__ __launch_bounds__(512,1) void phase1h(
    const float* __restrict__ enc, const float* __restrict__ zin,
    const float* __restrict__ W_ih, const float* __restrict__ b_ih,
    const float* __restrict__ W_dh, const float* __restrict__ b_dh,
    const float* __restrict__ b_hh,
    const float* __restrict__ lobs, const float* __restrict__ sg)
{
    extern __shared__ __align__(1024) char sm[];
    uint32_t sb=s2u(sm);
    const uint32_t oAh=0, oAl=12288, oBh=24576, oBl=49152;
    float* colb=(float*)(sm+73728); float* c58=(float*)(sm+74752); float* c59=(float*)(sm+75776);
    int tid=threadIdx.x, lane=tid&31, w=tid>>5;
    int wm=w>>3, wn=w&7;
    int m0=blockIdx.y*128, n0=blockIdx.x*256;

    if(tid<256){
        int j=n0+tid; float cb,w58=0.f,w59=0.f;
        if(j<G3){ cb=b_ih[j]+((j<256)?b_hh[j]:0.f);
                  w58=W_ih[(size_t)j*INd+1058]; w59=W_ih[(size_t)j*INd+1059]; }
        else cb=b_dh[j-G3];
        colb[tid]=cb; c58[tid]=w58; c59[tid]=w59;
    }

    int ra=tid>>2, kq=(tid&3)*4;
    int ma=m0+ra;
    const float* ae=enc+(size_t)ma*1024; const float* az=zin+(size_t)ma*32;
    int jb0=n0+ra, jb1=jb0+128;
    const float* bp0=(jb0<G3)?(W_ih+(size_t)jb0*INd):(W_dh+(size_t)(jb0-G3)*KZX);
    const float* bp1=(jb1<G3)?(W_ih+(size_t)jb1*INd):(W_dh+(size_t)(jb1-G3)*KZX);

    float acc[4][4][4];
    #pragma unroll
    for(int i=0;i<4;i++)
        #pragma unroll
        for(int j2=0;j2<4;j2++){ acc[i][j2][0]=0.f; acc[i][j2][1]=0.f; acc[i][j2][2]=0.f; acc[i][j2][3]=0.f; }

#define CVST(OH,OL,off,v) { \
    uint32_t _h0=pkbf((v).x,(v).y), _h1=pkbf((v).z,(v).w); \
    float _rx=(v).x-blo(_h0), _ry=(v).y-bhi(_h0), _rz=(v).z-blo(_h1), _rw=(v).w-bhi(_h1); \
    uint32_t _l0=pkbf(_rx,_ry), _l1=pkbf(_rz,_rw); \
    *(uint2*)(sm+(OH)+(off))=make_uint2(_h0,_h1); \
    *(uint2*)(sm+(OL)+(off))=make_uint2(_l0,_l1); }
#define LDT(kt) { int kk=(kt)*16+kq; \
    av=(kk<1024)?*(const float4*)(ae+kk):*(const float4*)(az+(kk-1024)); \
    b0v=*(const float4*)(bp0+kk); b1v=*(const float4*)(bp1+kk); }
#define STT(bf) { \
    CVST(oAh,oAl,(bf)*6144+ra*48+(tid&3)*8, av); \
    CVST(oBh,oBl,(bf)*12288+ra*48+(tid&3)*8, b0v); \
    CVST(oBh,oBl,(bf)*12288+(ra+128)*48+(tid&3)*8, b1v); }

    float4 av,b0v,b1v;
    LDT(0); STT(0);
    __syncthreads();

    for(int kt=0;kt<66;kt++){
        int buf=kt&1;
        if(kt<65) LDT(kt+1);
        uint32_t aBh=sb+oAh+buf*6144+(uint32_t)((wm*64+(lane&15))*48+(lane>>4)*16);
        uint32_t aBl=aBh+(oAl-oAh);
        uint32_t bOff=(uint32_t)((wn*32+(lane>>4)*8+(lane&7))*48+((lane>>3)&1)*16);
        uint32_t bBh=sb+oBh+buf*12288+bOff;
        uint32_t bBl=bBh+(oBl-oBh);
        uint32_t Bh0[4],Bh1[4],Bl0[4],Bl1[4];
        ldsm4(Bh0,bBh); ldsm4(Bh1,bBh+16*48);
        ldsm4(Bl0,bBl); ldsm4(Bl1,bBl+16*48);
        #pragma unroll
        for(int mt=0;mt<4;mt++){
            uint32_t Af[4],Alf[4];
            ldsm4(Af, aBh+(uint32_t)(mt*16*48));
            ldsm4(Alf,aBl+(uint32_t)(mt*16*48));
            #pragma unroll
            for(int nt=0;nt<4;nt++){
                uint32_t b0=(nt<2?Bh0:Bh1)[(nt&1)*2], b1=(nt<2?Bh0:Bh1)[(nt&1)*2+1];
                uint32_t l0=(nt<2?Bl0:Bl1)[(nt&1)*2], l1=(nt<2?Bl0:Bl1)[(nt&1)*2+1];
                mmabf(acc[mt][nt],Af,b0,b1);
                mmabf(acc[mt][nt],Alf,b0,b1);
                mmabf(acc[mt][nt],Af,l0,l1);
            }
        }
        __syncthreads();
        if(kt<65){ int nb=(kt+1)&1; STT(nb); }
        __syncthreads();
    }

    const float idt=1.f/4.8f;
    #pragma unroll
    for(int mt=0;mt<4;mt++){
        #pragma unroll
        for(int h=0;h<2;h++){
            int m=m0+wm*64+mt*16+(lane>>2)+8*h;
            float r0=(sg[2*m]-lobs[6*m])*idt, r1=(sg[2*m+1]-lobs[6*m+1])*idt;
            #pragma unroll
            for(int nt=0;nt<4;nt++){
                int jl=wn*32+nt*8+2*(lane&3);
                float vx=acc[mt][nt][2*h]  +colb[jl]  +r0*c58[jl]  +r1*c59[jl];
                float vy=acc[mt][nt][2*h+1]+colb[jl+1]+r0*c58[jl+1]+r1*c59[jl+1];
                *(float2*)&g_sc[(size_t)m*NC+n0+jl]=make_float2(vx,vy);
            }
        }
    }
#undef CVST
#undef LDT
#undef STT
}

// -------- Phase 2: 14-warp pairs + single-product fp16 + fp32 h-state --------
// 147 blocks x 448 threads (7 pairs x 16 rows = 112 rows/block, 2-way N split).
// h exchange: single fp16x2 plane, per-pair 16 rows x stride 68 u32.
// smem: WHs fp16[384*136] @0 (104448), was @104448 (3072), wm4 @107520 (2048),
//       bh2 @109568 (512), hx u32[7][16][68] @110080 (30464), px @140544 (3584).
#define SM2R 144128
__global__ __launch_bounds__(448,1) void phase2r(
    const float* __restrict__ W_hh, const float* __restrict__ W_ih,
    const float* __restrict__ b_hh,
    const float* __restrict__ W_mu, const float* __restrict__ b_mu,
    const float* __restrict__ W_std, const float* __restrict__ b_std,
    const float* __restrict__ lobs, const float* __restrict__ W_vel,
    const float* __restrict__ b_vel, const float* __restrict__ fut,
    float* __restrict__ out)
{
    extern __shared__ __align__(1024) char sm[];
    __half* WHs=(__half*)sm;
    float2* was=(float2*)(sm+104448);
    float4* wm4=(float4*)(sm+107520);
    float2* bh2=(float2*)(sm+109568);
    uint32_t* hx=(uint32_t*)(sm+110080);
    float2* px=(float2*)(sm+140544);
    int tid=threadIdx.x, lane=tid&31, wid=tid>>5;
    int pair=wid>>1, half=wid&1;
    int q=lane&3, rq=lane>>2;
    int rb=blockIdx.x*112+pair*16;
    int row0=rb+rq, row1=row0+8;
    bool active=rb<Bn;

    for(int i=tid;i<G3*128;i+=448){
        int n=i>>7,k=i&127;
        WHs[n*WS+k]=__float2half(W_hh[i]);
    }
    for(int i=tid;i<G3;i+=448)
        was[i]=make_float2(W_ih[(size_t)i*INd+1056],W_ih[(size_t)i*INd+1057]);
    if(tid<128) wm4[tid]=make_float4(W_mu[tid],W_mu[128+tid],W_std[tid],W_std[128+tid]);
    if(tid<64)  bh2[tid]=make_float2(b_hh[256+2*tid],b_hh[257+2*tid]);
    __syncthreads();
    if(!active) return;

    uint32_t sWH=s2u(WHs);
    uint32_t boff=(uint32_t)(((lane&7)*WS+(lane>>3)*8)*2);
    uint32_t hb=(uint32_t)(pair*1088);   // 16 rows * 68

    uint32_t Ah[8][4];
    float hp[32];
    #pragma unroll
    for(int kt=0;kt<8;kt++){
        #pragma unroll
        for(int rg=0;rg<4;rg++){
            int r=(rg&1)?row1:row0;
            int cb=kt*16+((rg>>1)*8)+2*q;
            float2 v=*(const float2*)&g_sc[(size_t)r*NC+G3+cb];
            Ah[kt][rg]=pkhf(v.x,v.y);
        }
    }
    #pragma unroll
    for(int c2=0;c2<8;c2++){
        int cg=half*8+c2;
        float2 v0=*(const float2*)&g_sc[(size_t)row0*NC+G3+8*cg+2*q];
        float2 v1=*(const float2*)&g_sc[(size_t)row1*NC+G3+8*cg+2*q];
        hp[c2*4+0]=v0.x; hp[c2*4+1]=v0.y;
        hp[c2*4+2]=v1.x; hp[c2*4+3]=v1.y;
    }
    float2 a0r0,a0r1;
    { float s0=b_vel[0],s1=b_vel[1],t0=s0,t1=s1;
      #pragma unroll
      for(int k=0;k<6;k++){
          float v0=__ldg(&lobs[row0*6+k]), v1=__ldg(&lobs[row1*6+k]);
          s0=fmaf(v0,W_vel[k],s0); s1=fmaf(v0,W_vel[6+k],s1);
          t0=fmaf(v1,W_vel[k],t0); t1=fmaf(v1,W_vel[6+k],t1); }
      a0r0=make_float2(s0,s1); a0r1=make_float2(t0,t1); }
    float bm0=b_mu[0],bm1=b_mu[1],bs0=b_std[0],bs1=b_std[1];

    for(int t=0;t<Tn;t++){
        float2 aR0,aR1;
        if(t==0){ aR0=a0r0; aR1=a0r1; }
        else { aR0=*(const float2*)&fut[((size_t)(t-1)*Bn+row0)*6+2];
               aR1=*(const float2*)&fut[((size_t)(t-1)*Bn+row1)*6+2]; }
        float p0=0,p1=0,p2=0,p3=0,p4=0,p5=0,p6=0,p7=0;
        #pragma unroll
        for(int c2=0;c2<8;c2++){
            int cg=half*8+c2;
            const float* gp0=&g_sc[(size_t)row0*NC+8*cg+2*q];
            const float* gp1=&g_sc[(size_t)row1*NC+8*cg+2*q];
            float2 gr0=*(const float2*)gp0, gz0=*(const float2*)(gp0+128), gn0=*(const float2*)(gp0+256);
            float2 gr1=*(const float2*)gp1, gz1=*(const float2*)(gp1+128), gn1=*(const float2*)(gp1+256);
            float cr[4]={0,0,0,0}, cz[4]={0,0,0,0}, cn[4]={0,0,0,0};
            #pragma unroll
            for(int k2=0;k2<4;k2++){
                uint32_t ab=(uint32_t)(((8*cg)*WS+k2*32)*2)+boff;
                uint32_t br[4],bz[4],bn[4];
                ldsm4(br, sWH+ab);
                ldsm4(bz, sWH+ab+128*WS*2);
                ldsm4(bn, sWH+ab+256*WS*2);
                #pragma unroll
                for(int h2=0;h2<2;h2++){
                    int kt=2*k2+h2;
                    mmahf(cr,Ah[kt],br[2*h2],br[2*h2+1]);
                    mmahf(cz,Ah[kt],bz[2*h2],bz[2*h2+1]);
                    mmahf(cn,Ah[kt],bn[2*h2],bn[2*h2+1]);
                }
            }
            float4 wr=*(const float4*)&was[8*cg+2*q];
            float4 wz=*(const float4*)&was[128+8*cg+2*q];
            float4 wn=*(const float4*)&was[256+8*cg+2*q];
            float2 bh=bh2[4*cg+q];
            float4 w0=wm4[8*cg+2*q], w1=wm4[8*cg+2*q+1];
            float r0x=sigf(gr0.x+aR0.x*wr.x+aR0.y*wr.y+cr[0]);
            float r0y=sigf(gr0.y+aR0.x*wr.z+aR0.y*wr.w+cr[1]);
            float r1x=sigf(gr1.x+aR1.x*wr.x+aR1.y*wr.y+cr[2]);
            float r1y=sigf(gr1.y+aR1.x*wr.z+aR1.y*wr.w+cr[3]);
            float z0x=sigf(gz0.x+aR0.x*wz.x+aR0.y*wz.y+cz[0]);
            float z0y=sigf(gz0.y+aR0.x*wz.z+aR0.y*wz.w+cz[1]);
            float z1x=sigf(gz1.x+aR1.x*wz.x+aR1.y*wz.y+cz[2]);
            float z1y=sigf(gz1.y+aR1.x*wz.z+aR1.y*wz.w+cz[3]);
            float n0x=tanha(gn0.x+aR0.x*wn.x+aR0.y*wn.y+r0x*(cn[0]+bh.x));
            float n0y=tanha(gn0.y+aR0.x*wn.z+aR0.y*wn.w+r0y*(cn[1]+bh.y));
            float n1x=tanha(gn1.x+aR1.x*wn.x+aR1.y*wn.y+r1x*(cn[2]+bh.x));
            float n1y=tanha(gn1.y+aR1.x*wn.z+aR1.y*wn.w+r1y*(cn[3]+bh.y));
            float h0x=(1.f-z0x)*n0x+z0x*hp[c2*4+0];
            float h0y=(1.f-z0y)*n0y+z0y*hp[c2*4+1];
            float h1x=(1.f-z1x)*n1x+z1x*hp[c2*4+2];
            float h1y=(1.f-z1y)*n1y+z1y*hp[c2*4+3];
            hp[c2*4+0]=h0x; hp[c2*4+1]=h0y;
            hp[c2*4+2]=h1x; hp[c2*4+3]=h1y;
            p0=fmaf(h0x,w0.x,p0); p0=fmaf(h0y,w1.x,p0);
            p1=fmaf(h0x,w0.y,p1); p1=fmaf(h0y,w1.y,p1);
            p2=fmaf(h0x,w0.z,p2); p2=fmaf(h0y,w1.z,p2);
            p3=fmaf(h0x,w0.w,p3); p3=fmaf(h0y,w1.w,p3);
            p4=fmaf(h1x,w0.x,p4); p4=fmaf(h1y,w1.x,p4);
            p5=fmaf(h1x,w0.y,p5); p5=fmaf(h1y,w1.y,p5);
            p6=fmaf(h1x,w0.z,p6); p6=fmaf(h1y,w1.z,p6);
            p7=fmaf(h1x,w0.w,p7); p7=fmaf(h1y,w1.w,p7);
            uint32_t wofs=hb+(uint32_t)(cg*4+q);
            hx[wofs+rq*68]    =pkhf(h0x,h0y);
            hx[wofs+(rq+8)*68]=pkhf(h1x,h1y);
        }
        p0+=__shfl_xor_sync(~0u,p0,1); p0+=__shfl_xor_sync(~0u,p0,2);
        p1+=__shfl_xor_sync(~0u,p1,1); p1+=__shfl_xor_sync(~0u,p1,2);
        p2+=__shfl_xor_sync(~0u,p2,1); p2+=__shfl_xor_sync(~0u,p2,2);
        p3+=__shfl_xor_sync(~0u,p3,1); p3+=__shfl_xor_sync(~0u,p3,2);
        p4+=__shfl_xor_sync(~0u,p4,1); p4+=__shfl_xor_sync(~0u,p4,2);
        p5+=__shfl_xor_sync(~0u,p5,1); p5+=__shfl_xor_sync(~0u,p5,2);
        p6+=__shfl_xor_sync(~0u,p6,1); p6+=__shfl_xor_sync(~0u,p6,2);
        p7+=__shfl_xor_sync(~0u,p7,1); p7+=__shfl_xor_sync(~0u,p7,2);
        float2 mine;
        if(q<2) mine=make_float2((q&1)?p4:p0,(q&1)?p5:p1);
        else    mine=make_float2((q&1)?p6:p2,(q&1)?p7:p3);
        px[pair*64+half*32+lane]=mine;
        asm volatile("bar.sync %0,64;"::"r"(pair+1):"memory");
        #pragma unroll
        for(int kt=0;kt<8;kt++){
            #pragma unroll
            for(int ch=0;ch<2;ch++){
                uint32_t pw=hb+(uint32_t)((2*kt+ch)*4+q);
                Ah[kt][ch*2  ]=hx[pw+rq*68];
                Ah[kt][ch*2+1]=hx[pw+(rq+8)*68];
            }
        }
        if(half==0){
            float2 other=px[pair*64+32+lane];
            float vx=mine.x+other.x, vy=mine.y+other.y;
            int orow=(q&1)?row1:row0;
            if(q<2)
                *(float2*)&out[(size_t)t*Bn*2+(size_t)orow*2]=make_float2(vx+bm0,vy+bm1);
            else
                *(float2*)&out[(size_t)(Tn+t)*Bn*2+(size_t)orow*2]=
                    make_float2(__expf(0.5f*(vx+bs0)),__expf(0.5f*(vy+bs1)));
        }
        asm volatile("bar.sync %0,64;"::"r"(pair+1):"memory");
    }
}

extern "C" void kernel_launch(void* const* d_in, const int* in_sizes, int n_in,
                              void* d_out, int out_size) {
    const float* lobs=(const float*)d_in[0];
    const float* enc =(const float*)d_in[1];
    const float* zin =(const float*)d_in[2];
    const float* sg  =(const float*)d_in[3];
    const float* fut =(const float*)d_in[4];
    const float* W_dh=(const float*)d_in[5];
    const float* b_dh=(const float*)d_in[6];
    const float* W_vel=(const float*)d_in[7];
    const float* b_vel=(const float*)d_in[8];
    const float* W_ih=(const float*)d_in[9];
    const float* b_ih=(const float*)d_in[10];
    const float* W_hh=(const float*)d_in[11];
    const float* b_hh=(const float*)d_in[12];
    const float* W_mu=(const float*)d_in[13];
    const float* b_mu=(const float*)d_in[14];
    const float* W_std=(const float*)d_in[15];
    const float* b_std=(const float*)d_in[16];
    float* out=(float*)d_out;

    cudaFuncSetAttribute(phase1h, cudaFuncAttributeMaxDynamicSharedMemorySize, P1SM);
    phase1h<<<dim3(2,128),512,P1SM>>>(enc,zin,W_ih,b_ih,W_dh,b_dh,b_hh,lobs,sg);

    cudaFuncSetAttribute(phase2r, cudaFuncAttributeMaxDynamicSharedMemorySize, SM2R);
    phase2r<<<147,448,SM2R>>>(W_hh,W_ih,b_hh,W_mu,b_mu,W_std,b_std,
                              lobs,W_vel,b_vel,fut,out);
}